// round 1
// baseline (speedup 1.0000x reference)
#include <cuda_runtime.h>
#include <math.h>

// Problem shape (fixed per reference)
#define BATCH 8
#define N1 2048
#define N2 2048
#define DIM 512

// Scratch: q [B,N1,D] (32MB) and attn [B,N1,N2] (128MB)
__device__ float g_q[(size_t)BATCH * N1 * DIM];
__device__ float g_attn[(size_t)BATCH * N1 * N2];

#define BM 128
#define BN 128
#define BK 16
#define PAD 4

// C[M,N] = sum_k A'[m,k] * B'[k,n]  (+ bias[n] if BIAS)
// AMODE 0: A'[m,k] = A[m*lda + k]   (row-major [M,K])
// AMODE 1: A'[m,k] = A[k*lda + m]   (row-major [K,M], i.e. transposed reduction)
// BMODE 0: B'[k,n] = B[k*ldb + n]   (row-major [K,N])
// BMODE 1: B'[k,n] = B[n*ldb + k]   (row-major [N,K], i.e. B^T)
template<int AMODE, int BMODE, bool BIAS>
__global__ __launch_bounds__(256)
void sgemm_kernel(const float* __restrict__ Aall, const float* __restrict__ Ball,
                  const float* __restrict__ bias, float* __restrict__ Call,
                  int M, int N, int K, int lda, int ldb,
                  long strideA, long strideB, long strideC)
{
    const int bz = blockIdx.z;
    const float* A = Aall + (long)bz * strideA;
    const float* B = Ball + (long)bz * strideB;
    float* C = Call + (long)bz * strideC;

    __shared__ float As[BK][BM + PAD];
    __shared__ float Bs[BK][BN + PAD];

    const int tid = threadIdx.x;
    const int tx = tid & 15;
    const int ty = tid >> 4;
    const int m0 = blockIdx.y * BM;
    const int n0 = blockIdx.x * BN;

    float acc[8][8];
    #pragma unroll
    for (int i = 0; i < 8; i++)
        #pragma unroll
        for (int j = 0; j < 8; j++) acc[i][j] = 0.f;

    for (int k0 = 0; k0 < K; k0 += BK) {
        // ---- load A tile into As[kk][mm] ----
        if (AMODE == 0) {
            int r = tid >> 2;            // 0..63
            int c = (tid & 3) * 4;       // 0,4,8,12
            float4 v0 = *(const float4*)&A[(long)(m0 + r) * lda + k0 + c];
            float4 v1 = *(const float4*)&A[(long)(m0 + r + 64) * lda + k0 + c];
            As[c + 0][r] = v0.x; As[c + 1][r] = v0.y;
            As[c + 2][r] = v0.z; As[c + 3][r] = v0.w;
            As[c + 0][r + 64] = v1.x; As[c + 1][r + 64] = v1.y;
            As[c + 2][r + 64] = v1.z; As[c + 3][r + 64] = v1.w;
        } else {
            int r = tid >> 5;            // 0..7
            int c = (tid & 31) * 4;      // 0..124
            *(float4*)&As[r][c]     = *(const float4*)&A[(long)(k0 + r) * lda + m0 + c];
            *(float4*)&As[r + 8][c] = *(const float4*)&A[(long)(k0 + r + 8) * lda + m0 + c];
        }
        // ---- load B tile into Bs[kk][nn] ----
        if (BMODE == 1) {
            int r = tid >> 2;
            int c = (tid & 3) * 4;
            float4 v0 = *(const float4*)&B[(long)(n0 + r) * ldb + k0 + c];
            float4 v1 = *(const float4*)&B[(long)(n0 + r + 64) * ldb + k0 + c];
            Bs[c + 0][r] = v0.x; Bs[c + 1][r] = v0.y;
            Bs[c + 2][r] = v0.z; Bs[c + 3][r] = v0.w;
            Bs[c + 0][r + 64] = v1.x; Bs[c + 1][r + 64] = v1.y;
            Bs[c + 2][r + 64] = v1.z; Bs[c + 3][r + 64] = v1.w;
        } else {
            int r = tid >> 5;
            int c = (tid & 31) * 4;
            *(float4*)&Bs[r][c]     = *(const float4*)&B[(long)(k0 + r) * ldb + n0 + c];
            *(float4*)&Bs[r + 8][c] = *(const float4*)&B[(long)(k0 + r + 8) * ldb + n0 + c];
        }
        __syncthreads();

        #pragma unroll
        for (int kk = 0; kk < BK; kk++) {
            float a[8], b[8];
            *(float4*)&a[0] = *(const float4*)&As[kk][ty * 4];
            *(float4*)&a[4] = *(const float4*)&As[kk][ty * 4 + 64];
            *(float4*)&b[0] = *(const float4*)&Bs[kk][tx * 4];
            *(float4*)&b[4] = *(const float4*)&Bs[kk][tx * 4 + 64];
            #pragma unroll
            for (int i = 0; i < 8; i++)
                #pragma unroll
                for (int j = 0; j < 8; j++)
                    acc[i][j] += a[i] * b[j];
        }
        __syncthreads();
    }

    // ---- epilogue ----
    const int na = n0 + tx * 4;
    const int nb = n0 + 64 + tx * 4;
    float4 bias_a = make_float4(0.f, 0.f, 0.f, 0.f);
    float4 bias_b = make_float4(0.f, 0.f, 0.f, 0.f);
    if (BIAS) {
        bias_a = *(const float4*)&bias[na];
        bias_b = *(const float4*)&bias[nb];
    }
    #pragma unroll
    for (int i = 0; i < 8; i++) {
        int m = m0 + ((i < 4) ? (ty * 4 + i) : (64 + ty * 4 + (i - 4)));
        float4 r0 = make_float4(acc[i][0], acc[i][1], acc[i][2], acc[i][3]);
        float4 r1 = make_float4(acc[i][4], acc[i][5], acc[i][6], acc[i][7]);
        if (BIAS) {
            r0.x += bias_a.x; r0.y += bias_a.y; r0.z += bias_a.z; r0.w += bias_a.w;
            r1.x += bias_b.x; r1.y += bias_b.y; r1.z += bias_b.z; r1.w += bias_b.w;
        }
        *(float4*)&C[(long)m * N + na] = r0;
        *(float4*)&C[(long)m * N + nb] = r1;
    }
}

// In-place softmax over rows of length 2048. One block per row, 256 threads x 8 elems.
__global__ __launch_bounds__(256)
void softmax2048_kernel(float* __restrict__ attn)
{
    const long row = blockIdx.x;
    float* p = attn + row * (long)N2;
    const int tid = threadIdx.x;

    float4 v0 = *(const float4*)(p + tid * 8);
    float4 v1 = *(const float4*)(p + tid * 8 + 4);

    float mx = fmaxf(fmaxf(fmaxf(v0.x, v0.y), fmaxf(v0.z, v0.w)),
                     fmaxf(fmaxf(v1.x, v1.y), fmaxf(v1.z, v1.w)));
    __shared__ float red[8];
    #pragma unroll
    for (int o = 16; o > 0; o >>= 1) mx = fmaxf(mx, __shfl_xor_sync(0xffffffffu, mx, o));
    if ((tid & 31) == 0) red[tid >> 5] = mx;
    __syncthreads();
    mx = red[0];
    #pragma unroll
    for (int i = 1; i < 8; i++) mx = fmaxf(mx, red[i]);
    __syncthreads();

    float e0 = expf(v0.x - mx), e1 = expf(v0.y - mx), e2 = expf(v0.z - mx), e3 = expf(v0.w - mx);
    float e4 = expf(v1.x - mx), e5 = expf(v1.y - mx), e6 = expf(v1.z - mx), e7 = expf(v1.w - mx);
    float s = ((e0 + e1) + (e2 + e3)) + ((e4 + e5) + (e6 + e7));
    #pragma unroll
    for (int o = 16; o > 0; o >>= 1) s += __shfl_xor_sync(0xffffffffu, s, o);
    if ((tid & 31) == 0) red[tid >> 5] = s;
    __syncthreads();
    s = 0.f;
    #pragma unroll
    for (int i = 0; i < 8; i++) s += red[i];
    const float inv = 1.0f / s;

    v0.x = e0 * inv; v0.y = e1 * inv; v0.z = e2 * inv; v0.w = e3 * inv;
    v1.x = e4 * inv; v1.y = e5 * inv; v1.z = e6 * inv; v1.w = e7 * inv;
    *(float4*)(p + tid * 8) = v0;
    *(float4*)(p + tid * 8 + 4) = v1;
}

extern "C" void kernel_launch(void* const* d_in, const int* in_sizes, int n_in,
                              void* d_out, int out_size)
{
    const float* input1 = (const float*)d_in[0];   // [B, N1, D]
    const float* input2 = (const float*)d_in[1];   // [B, N2, D]
    const float* W_w    = (const float*)d_in[2];   // [D, D] (out, in)
    const float* W_b    = (const float*)d_in[3];   // [D]

    float* out1 = (float*)d_out;                               // [B, N1, D]
    float* out2 = out1 + (long)BATCH * N1 * DIM;               // [B, N2, D]

    float* q    = nullptr;
    float* attn = nullptr;
    cudaGetSymbolAddress((void**)&q, g_q);
    cudaGetSymbolAddress((void**)&attn, g_attn);

    // K1: q = input1 @ W^T + b    [16384 x 512] = [16384 x 512] * [512 x 512]^T
    {
        dim3 grid(DIM / BN, (BATCH * N1) / BM, 1);
        sgemm_kernel<0, 1, true><<<grid, 256>>>(
            input1, W_w, W_b, q,
            BATCH * N1, DIM, DIM, /*lda*/DIM, /*ldb*/DIM,
            0L, 0L, 0L);
    }
    // K2: scores = q @ input2^T  per batch  [2048 x 2048]
    {
        dim3 grid(N2 / BN, N1 / BM, BATCH);
        sgemm_kernel<0, 1, false><<<grid, 256>>>(
            q, input2, nullptr, attn,
            N1, N2, DIM, /*lda*/DIM, /*ldb*/DIM,
            (long)N1 * DIM, (long)N2 * DIM, (long)N1 * N2);
    }
    // softmax over rows (in place)
    softmax2048_kernel<<<BATCH * N1, 256>>>(attn);

    // K4: out1 = attn @ input2   per batch  [2048 x 512]
    {
        dim3 grid(DIM / BN, N1 / BM, BATCH);
        sgemm_kernel<0, 0, false><<<grid, 256>>>(
            attn, input2, nullptr, out1,
            N1, DIM, N2, /*lda*/N2, /*ldb*/DIM,
            (long)N1 * N2, (long)N2 * DIM, (long)N1 * DIM);
    }
    // K5: out2 = attn^T @ input1  per batch  [2048 x 512]
    {
        dim3 grid(DIM / BN, N2 / BM, BATCH);
        sgemm_kernel<1, 0, false><<<grid, 256>>>(
            attn, input1, nullptr, out2,
            N2, DIM, N1, /*lda*/N2, /*ldb*/DIM,
            (long)N1 * N2, (long)N1 * DIM, (long)N2 * DIM);
    }
}

// round 3
// speedup vs baseline: 1.3085x; 1.3085x over previous
#include <cuda_runtime.h>
#include <cstdint>
#include <math.h>

#define BATCH 8
#define N1 2048
#define N2 2048
#define DIM 512

// Scratch: q [B,N1,D] (32MB) and attn [B,N1,N2] (128MB)
__device__ float g_q[(size_t)BATCH * N1 * DIM];
__device__ float g_attn[(size_t)BATCH * N1 * N2];

// ---------------- helpers ----------------
__device__ __forceinline__ uint32_t f2tf(float x) {
    uint32_t r;
    asm("cvt.rna.tf32.f32 %0, %1;" : "=r"(r) : "f"(x));
    return r;
}
__device__ __forceinline__ void split_tf32(float x, uint32_t& hi, uint32_t& lo) {
    hi = f2tf(x);
    lo = f2tf(x - __uint_as_float(hi));
}
__device__ __forceinline__ void mma_tf32(float* c, const uint32_t* a, const uint32_t* b) {
    asm volatile(
        "mma.sync.aligned.m16n8k8.row.col.f32.tf32.tf32.f32 "
        "{%0,%1,%2,%3}, {%4,%5,%6,%7}, {%8,%9}, {%0,%1,%2,%3};"
        : "+f"(c[0]), "+f"(c[1]), "+f"(c[2]), "+f"(c[3])
        : "r"(a[0]), "r"(a[1]), "r"(a[2]), "r"(a[3]), "r"(b[0]), "r"(b[1]));
}

// ---------------- tf32 mma.sync GEMM ----------------
// D[m,n] = sum_k A'[m,k]*B'[n,k] (+bias[n])
// XTRANS=0: X'[i,k] = X[i*ldx+k];  XTRANS=1: X'[i,k] = X[k*ldx+i]
// SPLIT: 3-term tf32 split (near-fp32); else single-pass tf32.
template<int ATRANS, int BTRANS, bool SPLIT, bool BIAS>
__global__ __launch_bounds__(256, 1)
void mma_gemm(const float* __restrict__ Aall, const float* __restrict__ Ball,
              const float* __restrict__ bias, float* __restrict__ Call,
              int K, int lda, int ldb, int ldc,
              long strideA, long strideB, long strideC)
{
    constexpr int S  = SPLIT ? 72 : 40;   // floats per smem row (data + pad)
    constexpr int TILEF = 128 * S;        // floats per operand tile
    extern __shared__ float smem[];
    // layout: [stage][A tile][B tile]
    const int tid = threadIdx.x;
    const int lane = tid & 31;
    const int wid = tid >> 5;
    const int wm = wid & 1;          // 2 warps in M
    const int wn = wid >> 1;         // 4 warps in N
    const int g = lane >> 2;         // 0..7
    const int t = lane & 3;          // 0..3
    const int m0 = blockIdx.y * 128;
    const int n0 = blockIdx.x * 128;
    const float* A = Aall + (long)blockIdx.z * strideA;
    const float* B = Ball + (long)blockIdx.z * strideB;
    float* C = Call + (long)blockIdx.z * strideC;

    float acc[4][4][4];
    #pragma unroll
    for (int i = 0; i < 4; i++)
        #pragma unroll
        for (int j = 0; j < 4; j++)
            #pragma unroll
            for (int e = 0; e < 4; e++) acc[i][j][e] = 0.f;

    float ra[16], rb[16];

    // ---- loaders ----
    auto load_regs = [&](int k0) {
        if (ATRANS == 0) {
            #pragma unroll
            for (int gg = 0; gg < 4; gg++) {
                int f = tid + 256 * gg;
                int r = f >> 3, c = (f & 7) * 4;
                *(float4*)&ra[gg * 4] = *(const float4*)&A[(long)(m0 + r) * lda + k0 + c];
            }
        } else {
            int m = tid & 127, kq = tid >> 7;
            #pragma unroll
            for (int gg = 0; gg < 4; gg++)
                #pragma unroll
                for (int e = 0; e < 4; e++)
                    ra[gg * 4 + e] = A[(long)(k0 + kq * 16 + gg * 4 + e) * lda + m0 + m];
        }
        if (BTRANS == 0) {
            #pragma unroll
            for (int gg = 0; gg < 4; gg++) {
                int f = tid + 256 * gg;
                int r = f >> 3, c = (f & 7) * 4;
                *(float4*)&rb[gg * 4] = *(const float4*)&B[(long)(n0 + r) * ldb + k0 + c];
            }
        } else {
            int n = tid & 127, kq = tid >> 7;
            #pragma unroll
            for (int gg = 0; gg < 4; gg++)
                #pragma unroll
                for (int e = 0; e < 4; e++)
                    rb[gg * 4 + e] = B[(long)(k0 + kq * 16 + gg * 4 + e) * ldb + n0 + n];
        }
    };

    auto store_tile = [&](int stage) {
        uint32_t* As = (uint32_t*)(smem + stage * 2 * TILEF);
        uint32_t* Bs = (uint32_t*)(smem + stage * 2 * TILEF + TILEF);
        if (SPLIT) {
            // hi/lo interleaved: element k -> cols 2k (hi), 2k+1 (lo)
            #pragma unroll
            for (int gg = 0; gg < 4; gg++) {
                int f = tid + 256 * gg;
                int r = f >> 3, c = (f & 7) * 4;
                uint32_t h[4], l[4];
                #pragma unroll
                for (int e = 0; e < 4; e++) split_tf32(ra[gg * 4 + e], h[e], l[e]);
                uint4* p = (uint4*)&As[r * S + 2 * c];
                p[0] = make_uint4(h[0], l[0], h[1], l[1]);
                p[1] = make_uint4(h[2], l[2], h[3], l[3]);
                #pragma unroll
                for (int e = 0; e < 4; e++) split_tf32(rb[gg * 4 + e], h[e], l[e]);
                uint4* q = (uint4*)&Bs[r * S + 2 * c];
                q[0] = make_uint4(h[0], l[0], h[1], l[1]);
                q[1] = make_uint4(h[2], l[2], h[3], l[3]);
            }
        } else {
            if (ATRANS == 0) {
                #pragma unroll
                for (int gg = 0; gg < 4; gg++) {
                    int f = tid + 256 * gg;
                    int r = f >> 3, c = (f & 7) * 4;
                    uint4 v = make_uint4(f2tf(ra[gg * 4]), f2tf(ra[gg * 4 + 1]),
                                         f2tf(ra[gg * 4 + 2]), f2tf(ra[gg * 4 + 3]));
                    *(uint4*)&As[r * S + c] = v;
                }
            } else {
                int m = tid & 127, kq = tid >> 7;
                #pragma unroll
                for (int gg = 0; gg < 4; gg++) {
                    uint4 v = make_uint4(f2tf(ra[gg * 4]), f2tf(ra[gg * 4 + 1]),
                                         f2tf(ra[gg * 4 + 2]), f2tf(ra[gg * 4 + 3]));
                    *(uint4*)&As[m * S + kq * 16 + gg * 4] = v;
                }
            }
            if (BTRANS == 0) {
                #pragma unroll
                for (int gg = 0; gg < 4; gg++) {
                    int f = tid + 256 * gg;
                    int r = f >> 3, c = (f & 7) * 4;
                    uint4 v = make_uint4(f2tf(rb[gg * 4]), f2tf(rb[gg * 4 + 1]),
                                         f2tf(rb[gg * 4 + 2]), f2tf(rb[gg * 4 + 3]));
                    *(uint4*)&Bs[r * S + c] = v;
                }
            } else {
                int n = tid & 127, kq = tid >> 7;
                #pragma unroll
                for (int gg = 0; gg < 4; gg++) {
                    uint4 v = make_uint4(f2tf(rb[gg * 4]), f2tf(rb[gg * 4 + 1]),
                                         f2tf(rb[gg * 4 + 2]), f2tf(rb[gg * 4 + 3]));
                    *(uint4*)&Bs[n * S + kq * 16 + gg * 4] = v;
                }
            }
        }
    };

    auto compute = [&](int stage) {
        const uint32_t* As = (const uint32_t*)(smem + stage * 2 * TILEF);
        const uint32_t* Bs = (const uint32_t*)(smem + stage * 2 * TILEF + TILEF);
        const int arow = wm * 64;
        const int brow = wn * 32;
        #pragma unroll
        for (int ks = 0; ks < 4; ks++) {
            if (SPLIT) {
                uint32_t ah[4][4], al[4][4], bh[4][2], bl[4][2];
                const int col2 = 2 * (ks * 8 + t);
                #pragma unroll
                for (int mt = 0; mt < 4; mt++) {
                    const uint32_t* base = &As[(arow + mt * 16 + g) * S];
                    uint2 p0 = *(const uint2*)&base[col2];
                    uint2 p1 = *(const uint2*)&base[8 * S + col2];
                    uint2 p2 = *(const uint2*)&base[col2 + 8];
                    uint2 p3 = *(const uint2*)&base[8 * S + col2 + 8];
                    ah[mt][0] = p0.x; al[mt][0] = p0.y;
                    ah[mt][1] = p1.x; al[mt][1] = p1.y;
                    ah[mt][2] = p2.x; al[mt][2] = p2.y;
                    ah[mt][3] = p3.x; al[mt][3] = p3.y;
                }
                #pragma unroll
                for (int nt = 0; nt < 4; nt++) {
                    const uint32_t* base = &Bs[(brow + nt * 8 + g) * S];
                    uint2 p0 = *(const uint2*)&base[col2];
                    uint2 p1 = *(const uint2*)&base[col2 + 8];
                    bh[nt][0] = p0.x; bl[nt][0] = p0.y;
                    bh[nt][1] = p1.x; bl[nt][1] = p1.y;
                }
                #pragma unroll
                for (int mt = 0; mt < 4; mt++)
                    #pragma unroll
                    for (int nt = 0; nt < 4; nt++) {
                        mma_tf32(acc[mt][nt], ah[mt], bh[nt]);
                        mma_tf32(acc[mt][nt], al[mt], bh[nt]);
                        mma_tf32(acc[mt][nt], ah[mt], bl[nt]);
                    }
            } else {
                uint32_t af[4][4], bf[4][2];
                const int col = ks * 8 + t;
                #pragma unroll
                for (int mt = 0; mt < 4; mt++) {
                    const uint32_t* base = &As[(arow + mt * 16 + g) * S];
                    af[mt][0] = base[col];
                    af[mt][1] = base[8 * S + col];
                    af[mt][2] = base[col + 4];
                    af[mt][3] = base[8 * S + col + 4];
                }
                #pragma unroll
                for (int nt = 0; nt < 4; nt++) {
                    const uint32_t* base = &Bs[(brow + nt * 8 + g) * S];
                    bf[nt][0] = base[col];
                    bf[nt][1] = base[col + 4];
                }
                #pragma unroll
                for (int mt = 0; mt < 4; mt++)
                    #pragma unroll
                    for (int nt = 0; nt < 4; nt++)
                        mma_tf32(acc[mt][nt], af[mt], bf[nt]);
            }
        }
    };

    // ---- pipelined mainloop ----
    const int iters = K >> 5;
    load_regs(0);
    store_tile(0);
    if (iters > 1) load_regs(32);
    __syncthreads();
    for (int it = 0; it < iters; ++it) {
        if (it + 1 < iters) store_tile((it + 1) & 1);
        if (it + 2 < iters) load_regs((it + 2) * 32);
        compute(it & 1);
        __syncthreads();
    }

    // ---- epilogue ----
    #pragma unroll
    for (int mt = 0; mt < 4; mt++) {
        const int r0 = m0 + wm * 64 + mt * 16 + g;
        #pragma unroll
        for (int nt = 0; nt < 4; nt++) {
            const int col = n0 + wn * 32 + nt * 8 + 2 * t;
            float b0 = 0.f, b1 = 0.f;
            if (BIAS) { b0 = bias[col]; b1 = bias[col + 1]; }
            *(float2*)&C[(long)r0 * ldc + col] =
                make_float2(acc[mt][nt][0] + b0, acc[mt][nt][1] + b1);
            *(float2*)&C[(long)(r0 + 8) * ldc + col] =
                make_float2(acc[mt][nt][2] + b0, acc[mt][nt][3] + b1);
        }
    }
}

// ---------------- softmax over rows of 2048 (in place) ----------------
__global__ __launch_bounds__(256)
void softmax2048_kernel(float* __restrict__ attn)
{
    const long row = blockIdx.x;
    float* p = attn + row * (long)N2;
    const int tid = threadIdx.x;

    float4 v0 = *(const float4*)(p + tid * 8);
    float4 v1 = *(const float4*)(p + tid * 8 + 4);

    float mx = fmaxf(fmaxf(fmaxf(v0.x, v0.y), fmaxf(v0.z, v0.w)),
                     fmaxf(fmaxf(v1.x, v1.y), fmaxf(v1.z, v1.w)));
    __shared__ float red[8];
    #pragma unroll
    for (int o = 16; o > 0; o >>= 1) mx = fmaxf(mx, __shfl_xor_sync(0xffffffffu, mx, o));
    if ((tid & 31) == 0) red[tid >> 5] = mx;
    __syncthreads();
    mx = red[0];
    #pragma unroll
    for (int i = 1; i < 8; i++) mx = fmaxf(mx, red[i]);
    __syncthreads();

    float e0 = expf(v0.x - mx), e1 = expf(v0.y - mx), e2 = expf(v0.z - mx), e3 = expf(v0.w - mx);
    float e4 = expf(v1.x - mx), e5 = expf(v1.y - mx), e6 = expf(v1.z - mx), e7 = expf(v1.w - mx);
    float s = ((e0 + e1) + (e2 + e3)) + ((e4 + e5) + (e6 + e7));
    #pragma unroll
    for (int o = 16; o > 0; o >>= 1) s += __shfl_xor_sync(0xffffffffu, s, o);
    if ((tid & 31) == 0) red[tid >> 5] = s;
    __syncthreads();
    s = 0.f;
    #pragma unroll
    for (int i = 0; i < 8; i++) s += red[i];
    const float inv = 1.0f / s;

    v0.x = e0 * inv; v0.y = e1 * inv; v0.z = e2 * inv; v0.w = e3 * inv;
    v1.x = e4 * inv; v1.y = e5 * inv; v1.z = e6 * inv; v1.w = e7 * inv;
    *(float4*)(p + tid * 8) = v0;
    *(float4*)(p + tid * 8 + 4) = v1;
}

// ---------------- launcher ----------------
extern "C" void kernel_launch(void* const* d_in, const int* in_sizes, int n_in,
                              void* d_out, int out_size)
{
    const float* input1 = (const float*)d_in[0];   // [B, N1, D]
    const float* input2 = (const float*)d_in[1];   // [B, N2, D]
    const float* W_w    = (const float*)d_in[2];   // [D, D]
    const float* W_b    = (const float*)d_in[3];   // [D]

    float* out1 = (float*)d_out;                    // [B, N1, D]
    float* out2 = out1 + (long)BATCH * N1 * DIM;    // [B, N2, D]

    float* q = nullptr;
    float* attn = nullptr;
    cudaGetSymbolAddress((void**)&q, g_q);
    cudaGetSymbolAddress((void**)&attn, g_attn);

    const int SMEM_SPLIT  = 2 * 2 * 128 * 72 * 4;   // 147456
    const int SMEM_SINGLE = 2 * 2 * 128 * 40 * 4;   // 81920

    cudaFuncSetAttribute(mma_gemm<0, 0, true, true>,   cudaFuncAttributeMaxDynamicSharedMemorySize, SMEM_SPLIT);
    cudaFuncSetAttribute(mma_gemm<0, 0, true, false>,  cudaFuncAttributeMaxDynamicSharedMemorySize, SMEM_SPLIT);
    cudaFuncSetAttribute(mma_gemm<0, 1, false, false>, cudaFuncAttributeMaxDynamicSharedMemorySize, SMEM_SINGLE);
    cudaFuncSetAttribute(mma_gemm<1, 1, false, false>, cudaFuncAttributeMaxDynamicSharedMemorySize, SMEM_SINGLE);

    // K1: q = input1 @ W^T + b    [16384, 512], K=512  (3-term split)
    mma_gemm<0, 0, true, true><<<dim3(DIM / 128, (BATCH * N1) / 128, 1), 256, SMEM_SPLIT>>>(
        input1, W_w, W_b, q, DIM, DIM, DIM, DIM, 0L, 0L, 0L);

    // K2: scores = q @ input2^T   per batch [2048, 2048], K=512  (3-term split)
    mma_gemm<0, 0, true, false><<<dim3(N2 / 128, N1 / 128, BATCH), 256, SMEM_SPLIT>>>(
        q, input2, nullptr, attn, DIM, DIM, DIM, N2,
        (long)N1 * DIM, (long)N2 * DIM, (long)N1 * N2);

    // softmax rows (in place)
    softmax2048_kernel<<<BATCH * N1, 256>>>(attn);

    // K4: out1 = attn @ input2    per batch [2048, 512], K=2048  (single tf32)
    mma_gemm<0, 1, false, false><<<dim3(DIM / 128, N1 / 128, BATCH), 256, SMEM_SINGLE>>>(
        attn, input2, nullptr, out1, N2, N2, DIM, DIM,
        (long)N1 * N2, (long)N2 * DIM, (long)N1 * DIM);

    // K5: out2 = attn^T @ input1  per batch [2048, 512], K=2048  (single tf32)
    mma_gemm<1, 1, false, false><<<dim3(DIM / 128, N2 / 128, BATCH), 256, SMEM_SINGLE>>>(
        attn, input1, nullptr, out2, N1, N2, DIM, DIM,
        (long)N1 * N2, (long)N1 * DIM, (long)N2 * DIM);
}

// round 4
// speedup vs baseline: 1.8426x; 1.4082x over previous
#include <cuda_runtime.h>
#include <cstdint>
#include <math.h>

#define BATCH 8
#define N1 2048
#define N2 2048
#define DIM 512

// Scratch: q [B,N1,D] (32MB) and attn [B,N1,N2] (128MB)
__device__ float g_q[(size_t)BATCH * N1 * DIM];
__device__ float g_attn[(size_t)BATCH * N1 * N2];

// ---------------- helpers ----------------
__device__ __forceinline__ uint32_t smem_u32(const void* p) {
    uint32_t a;
    asm("{ .reg .u64 t; cvta.to.shared.u64 t, %1; cvt.u32.u64 %0, t; }" : "=r"(a) : "l"(p));
    return a;
}
__device__ __forceinline__ uint32_t f2tf(float x) {
    uint32_t r;
    asm("cvt.rna.tf32.f32 %0, %1;" : "=r"(r) : "f"(x));
    return r;
}
__device__ __forceinline__ void split_tf32(float x, uint32_t& hi, uint32_t& lo) {
    hi = f2tf(x);
    lo = f2tf(x - __uint_as_float(hi));
}
__device__ __forceinline__ void mma_tf32(float* c, const uint32_t* a, const uint32_t* b) {
    asm volatile(
        "mma.sync.aligned.m16n8k8.row.col.f32.tf32.tf32.f32 "
        "{%0,%1,%2,%3}, {%4,%5,%6,%7}, {%8,%9}, {%0,%1,%2,%3};"
        : "+f"(c[0]), "+f"(c[1]), "+f"(c[2]), "+f"(c[3])
        : "r"(a[0]), "r"(a[1]), "r"(a[2]), "r"(a[3]), "r"(b[0]), "r"(b[1]));
}
__device__ __forceinline__ void cp16(uint32_t dst, const void* src) {
    asm volatile("cp.async.cg.shared.global [%0], [%1], 16;" :: "r"(dst), "l"(src));
}
__device__ __forceinline__ void cp_commit() {
    asm volatile("cp.async.commit_group;" ::: "memory");
}

// ---------------- tf32 mma.sync GEMM, 4-stage cp.async pipeline ----------------
// D[m,n] = sum_k A'[m,k]*B'[n,k] (+bias[n])
// XTRANS=0: X'[i,k] = X[i*ldx+k]  -> smem tile [128 rows][36 floats]
// XTRANS=1: X'[i,k] = X[k*ldx+i]  -> smem tile [32 rows(k)][136 floats]
// SPLIT: 3-term tf32 split (requires ATRANS==BTRANS==0); else single-pass tf32.
template<int ATRANS, int BTRANS, bool SPLIT, bool BIAS>
__global__ __launch_bounds__(256, 1)
void mma_gemm(const float* __restrict__ Aall, const float* __restrict__ Ball,
              const float* __restrict__ bias, float* __restrict__ Call,
              int K, int lda, int ldb, int ldc,
              long strideA, long strideB, long strideC)
{
    constexpr int NS = 4;
    constexpr int SA = ATRANS ? 136 : 36;
    constexpr int SB = BTRANS ? 136 : 36;
    constexpr int ABYTES = (ATRANS ? 32 * 136 : 128 * 36) * 4;
    constexpr int BBYTES = (BTRANS ? 32 * 136 : 128 * 36) * 4;
    constexpr int STAGE = ABYTES + BBYTES;

    extern __shared__ char smem_raw[];
    const uint32_t sbase = smem_u32(smem_raw);

    const int tid = threadIdx.x;
    const int lane = tid & 31;
    const int wid = tid >> 5;
    const int wm = wid & 1;          // 2 warps in M (64 rows each)
    const int wn = wid >> 1;         // 4 warps in N (32 cols each)
    const int g = lane >> 2;         // 0..7
    const int t = lane & 3;          // 0..3
    const int m0 = blockIdx.y * 128;
    const int n0 = blockIdx.x * 128;
    const float* A = Aall + (long)blockIdx.z * strideA;
    const float* B = Ball + (long)blockIdx.z * strideB;
    float* C = Call + (long)blockIdx.z * strideC;

    float acc[4][4][4];
    #pragma unroll
    for (int i = 0; i < 4; i++)
        #pragma unroll
        for (int j = 0; j < 4; j++)
            #pragma unroll
            for (int e = 0; e < 4; e++) acc[i][j][e] = 0.f;

    const int iters = K >> 5;

    auto issue = [&](int it) {
        const int k0 = it << 5;
        const uint32_t st = sbase + (it & (NS - 1)) * STAGE;
        if (ATRANS == 0) {
            #pragma unroll
            for (int i = 0; i < 4; i++) {
                int ch = tid + 256 * i;
                int r = ch >> 3, c = ch & 7;
                cp16(st + r * (SA * 4) + c * 16, &A[(long)(m0 + r) * lda + k0 + c * 4]);
            }
        } else {
            #pragma unroll
            for (int i = 0; i < 4; i++) {
                int ch = tid + 256 * i;
                int r = ch >> 5, c = ch & 31;
                cp16(st + r * (SA * 4) + c * 16, &A[(long)(k0 + r) * lda + m0 + c * 4]);
            }
        }
        if (BTRANS == 0) {
            #pragma unroll
            for (int i = 0; i < 4; i++) {
                int ch = tid + 256 * i;
                int r = ch >> 3, c = ch & 7;
                cp16(st + ABYTES + r * (SB * 4) + c * 16, &B[(long)(n0 + r) * ldb + k0 + c * 4]);
            }
        } else {
            #pragma unroll
            for (int i = 0; i < 4; i++) {
                int ch = tid + 256 * i;
                int r = ch >> 5, c = ch & 31;
                cp16(st + ABYTES + r * (SB * 4) + c * 16, &B[(long)(k0 + r) * ldb + n0 + c * 4]);
            }
        }
    };

    auto compute = [&](int stage) {
        const float* As = (const float*)(smem_raw + (size_t)stage * STAGE);
        const float* Bs = (const float*)(smem_raw + (size_t)stage * STAGE + ABYTES);
        const int ar = wm * 64;
        const int br = wn * 32;
        #pragma unroll
        for (int ks = 0; ks < 4; ks++) {
            const int col = ks * 8 + t;
            if (SPLIT) {
                uint32_t ah[4][4], al[4][4], bh[4][2], bl[4][2];
                #pragma unroll
                for (int mt = 0; mt < 4; mt++) {
                    const float* p0 = &As[(ar + mt * 16 + g) * 36];
                    const float* p1 = &As[(ar + mt * 16 + g + 8) * 36];
                    split_tf32(p0[col],     ah[mt][0], al[mt][0]);
                    split_tf32(p1[col],     ah[mt][1], al[mt][1]);
                    split_tf32(p0[col + 4], ah[mt][2], al[mt][2]);
                    split_tf32(p1[col + 4], ah[mt][3], al[mt][3]);
                }
                #pragma unroll
                for (int nt = 0; nt < 4; nt++) {
                    const float* p = &Bs[(br + nt * 8 + g) * 36];
                    split_tf32(p[col],     bh[nt][0], bl[nt][0]);
                    split_tf32(p[col + 4], bh[nt][1], bl[nt][1]);
                }
                #pragma unroll
                for (int mt = 0; mt < 4; mt++)
                    #pragma unroll
                    for (int nt = 0; nt < 4; nt++) {
                        mma_tf32(acc[mt][nt], ah[mt], bh[nt]);
                        mma_tf32(acc[mt][nt], al[mt], bh[nt]);
                        mma_tf32(acc[mt][nt], ah[mt], bl[nt]);
                    }
            } else {
                uint32_t af[4][4], bf[4][2];
                #pragma unroll
                for (int mt = 0; mt < 4; mt++) {
                    if (ATRANS == 0) {
                        const float* p0 = &As[(ar + mt * 16 + g) * 36];
                        const float* p1 = &As[(ar + mt * 16 + g + 8) * 36];
                        af[mt][0] = f2tf(p0[col]);
                        af[mt][1] = f2tf(p1[col]);
                        af[mt][2] = f2tf(p0[col + 4]);
                        af[mt][3] = f2tf(p1[col + 4]);
                    } else {
                        const float* p0 = &As[col * 136 + ar + mt * 16 + g];
                        const float* p1 = &As[(col + 4) * 136 + ar + mt * 16 + g];
                        af[mt][0] = f2tf(p0[0]);
                        af[mt][1] = f2tf(p0[8]);
                        af[mt][2] = f2tf(p1[0]);
                        af[mt][3] = f2tf(p1[8]);
                    }
                }
                #pragma unroll
                for (int nt = 0; nt < 4; nt++) {
                    if (BTRANS == 0) {
                        const float* p = &Bs[(br + nt * 8 + g) * 36];
                        bf[nt][0] = f2tf(p[col]);
                        bf[nt][1] = f2tf(p[col + 4]);
                    } else {
                        bf[nt][0] = f2tf(Bs[col * 136 + br + nt * 8 + g]);
                        bf[nt][1] = f2tf(Bs[(col + 4) * 136 + br + nt * 8 + g]);
                    }
                }
                #pragma unroll
                for (int mt = 0; mt < 4; mt++)
                    #pragma unroll
                    for (int nt = 0; nt < 4; nt++)
                        mma_tf32(acc[mt][nt], af[mt], bf[nt]);
            }
        }
    };

    // ---- prologue: fill NS-1 stages ----
    #pragma unroll
    for (int s = 0; s < NS - 1; s++) {
        issue(s);
        cp_commit();
    }

    // ---- mainloop: one sync per iteration ----
    for (int it = 0; it < iters; ++it) {
        asm volatile("cp.async.wait_group %0;" :: "n"(NS - 2) : "memory");
        __syncthreads();
        if (it + NS - 1 < iters) issue(it + NS - 1);
        cp_commit();
        compute(it & (NS - 1));
    }

    // ---- epilogue ----
    #pragma unroll
    for (int mt = 0; mt < 4; mt++) {
        const int r0 = m0 + wm * 64 + mt * 16 + g;
        #pragma unroll
        for (int nt = 0; nt < 4; nt++) {
            const int col = n0 + wn * 32 + nt * 8 + 2 * t;
            float b0 = 0.f, b1 = 0.f;
            if (BIAS) { b0 = bias[col]; b1 = bias[col + 1]; }
            *(float2*)&C[(long)r0 * ldc + col] =
                make_float2(acc[mt][nt][0] + b0, acc[mt][nt][1] + b1);
            *(float2*)&C[(long)(r0 + 8) * ldc + col] =
                make_float2(acc[mt][nt][2] + b0, acc[mt][nt][3] + b1);
        }
    }
}

// ---------------- softmax over rows of 2048 (in place) ----------------
__global__ __launch_bounds__(256)
void softmax2048_kernel(float* __restrict__ attn)
{
    const long row = blockIdx.x;
    float* p = attn + row * (long)N2;
    const int tid = threadIdx.x;

    float4 v0 = *(const float4*)(p + tid * 8);
    float4 v1 = *(const float4*)(p + tid * 8 + 4);

    float mx = fmaxf(fmaxf(fmaxf(v0.x, v0.y), fmaxf(v0.z, v0.w)),
                     fmaxf(fmaxf(v1.x, v1.y), fmaxf(v1.z, v1.w)));
    __shared__ float red[8];
    #pragma unroll
    for (int o = 16; o > 0; o >>= 1) mx = fmaxf(mx, __shfl_xor_sync(0xffffffffu, mx, o));
    if ((tid & 31) == 0) red[tid >> 5] = mx;
    __syncthreads();
    mx = red[0];
    #pragma unroll
    for (int i = 1; i < 8; i++) mx = fmaxf(mx, red[i]);
    __syncthreads();

    float e0 = expf(v0.x - mx), e1 = expf(v0.y - mx), e2 = expf(v0.z - mx), e3 = expf(v0.w - mx);
    float e4 = expf(v1.x - mx), e5 = expf(v1.y - mx), e6 = expf(v1.z - mx), e7 = expf(v1.w - mx);
    float s = ((e0 + e1) + (e2 + e3)) + ((e4 + e5) + (e6 + e7));
    #pragma unroll
    for (int o = 16; o > 0; o >>= 1) s += __shfl_xor_sync(0xffffffffu, s, o);
    if ((tid & 31) == 0) red[tid >> 5] = s;
    __syncthreads();
    s = 0.f;
    #pragma unroll
    for (int i = 0; i < 8; i++) s += red[i];
    const float inv = 1.0f / s;

    v0.x = e0 * inv; v0.y = e1 * inv; v0.z = e2 * inv; v0.w = e3 * inv;
    v1.x = e4 * inv; v1.y = e5 * inv; v1.z = e6 * inv; v1.w = e7 * inv;
    *(float4*)(p + tid * 8) = v0;
    *(float4*)(p + tid * 8 + 4) = v1;
}

// ---------------- launcher ----------------
extern "C" void kernel_launch(void* const* d_in, const int* in_sizes, int n_in,
                              void* d_out, int out_size)
{
    const float* input1 = (const float*)d_in[0];   // [B, N1, D]
    const float* input2 = (const float*)d_in[1];   // [B, N2, D]
    const float* W_w    = (const float*)d_in[2];   // [D, D]
    const float* W_b    = (const float*)d_in[3];   // [D]

    float* out1 = (float*)d_out;                    // [B, N1, D]
    float* out2 = out1 + (long)BATCH * N1 * DIM;    // [B, N2, D]

    float* q = nullptr;
    float* attn = nullptr;
    cudaGetSymbolAddress((void**)&q, g_q);
    cudaGetSymbolAddress((void**)&attn, g_attn);

    // smem: 4 stages x (A tile + B tile)
    const int SM_00 = 4 * 2 * 128 * 36 * 4;                 // 147456 (K1, K2)
    const int SM_01 = 4 * (128 * 36 + 32 * 136) * 4;        // 143360 (K4)
    const int SM_11 = 4 * 2 * 32 * 136 * 4;                 // 139264 (K5)

    cudaFuncSetAttribute(mma_gemm<0, 0, true, true>,   cudaFuncAttributeMaxDynamicSharedMemorySize, SM_00);
    cudaFuncSetAttribute(mma_gemm<0, 0, true, false>,  cudaFuncAttributeMaxDynamicSharedMemorySize, SM_00);
    cudaFuncSetAttribute(mma_gemm<0, 1, false, false>, cudaFuncAttributeMaxDynamicSharedMemorySize, SM_01);
    cudaFuncSetAttribute(mma_gemm<1, 1, false, false>, cudaFuncAttributeMaxDynamicSharedMemorySize, SM_11);

    // K1: q = input1 @ W^T + b    [16384, 512], K=512  (3-term split)
    mma_gemm<0, 0, true, true><<<dim3(DIM / 128, (BATCH * N1) / 128, 1), 256, SM_00>>>(
        input1, W_w, W_b, q, DIM, DIM, DIM, DIM, 0L, 0L, 0L);

    // K2: scores = q @ input2^T   per batch [2048, 2048], K=512  (3-term split)
    mma_gemm<0, 0, true, false><<<dim3(N2 / 128, N1 / 128, BATCH), 256, SM_00>>>(
        q, input2, nullptr, attn, DIM, DIM, DIM, N2,
        (long)N1 * DIM, (long)N2 * DIM, (long)N1 * N2);

    // softmax rows (in place)
    softmax2048_kernel<<<BATCH * N1, 256>>>(attn);

    // K4: out1 = attn @ input2    per batch [2048, 512], K=2048  (single tf32)
    mma_gemm<0, 1, false, false><<<dim3(DIM / 128, N1 / 128, BATCH), 256, SM_01>>>(
        attn, input2, nullptr, out1, N2, N2, DIM, DIM,
        (long)N1 * N2, (long)N2 * DIM, (long)N1 * DIM);

    // K5: out2 = attn^T @ input1  per batch [2048, 512], K=2048  (single tf32)
    mma_gemm<1, 1, false, false><<<dim3(DIM / 128, N2 / 128, BATCH), 256, SM_11>>>(
        attn, input1, nullptr, out2, N1, N2, DIM, DIM,
        (long)N1 * N2, (long)N1 * DIM, (long)N2 * DIM);
}

// round 5
// speedup vs baseline: 2.5260x; 1.3709x over previous
#include <cuda_runtime.h>
#include <cuda_fp16.h>
#include <cstdint>
#include <math.h>

#define BATCH 8
#define N1 2048
#define N2 2048
#define DIM 512

// Scratch: q [B,N1,D] (32MB) and attn [B,N1,N2] (128MB)
__device__ float g_q[(size_t)BATCH * N1 * DIM];
__device__ float g_attn[(size_t)BATCH * N1 * N2];

// ---------------- helpers ----------------
__device__ __forceinline__ uint32_t smem_u32(const void* p) {
    uint32_t a;
    asm("{ .reg .u64 t; cvta.to.shared.u64 t, %1; cvt.u32.u64 %0, t; }" : "=r"(a) : "l"(p));
    return a;
}
__device__ __forceinline__ uint32_t f2tf(float x) {
    uint32_t r;
    asm("cvt.rna.tf32.f32 %0, %1;" : "=r"(r) : "f"(x));
    return r;
}
__device__ __forceinline__ void mma_tf32(float* c, const uint32_t* a, const uint32_t* b) {
    asm volatile(
        "mma.sync.aligned.m16n8k8.row.col.f32.tf32.tf32.f32 "
        "{%0,%1,%2,%3}, {%4,%5,%6,%7}, {%8,%9}, {%0,%1,%2,%3};"
        : "+f"(c[0]), "+f"(c[1]), "+f"(c[2]), "+f"(c[3])
        : "r"(a[0]), "r"(a[1]), "r"(a[2]), "r"(a[3]), "r"(b[0]), "r"(b[1]));
}
__device__ __forceinline__ void mma_f16(float* c, const uint32_t* a, const uint32_t* b) {
    asm volatile(
        "mma.sync.aligned.m16n8k16.row.col.f32.f16.f16.f32 "
        "{%0,%1,%2,%3}, {%4,%5,%6,%7}, {%8,%9}, {%0,%1,%2,%3};"
        : "+f"(c[0]), "+f"(c[1]), "+f"(c[2]), "+f"(c[3])
        : "r"(a[0]), "r"(a[1]), "r"(a[2]), "r"(a[3]), "r"(b[0]), "r"(b[1]));
}
// split float2 -> hi f16x2 + lo f16x2 (3-term Ozaki-style split)
__device__ __forceinline__ void split_h2(float2 v, uint32_t& hi, uint32_t& lo) {
    __half2 h = __float22half2_rn(v);
    hi = *(uint32_t*)&h;
    float2 hf = __half22float2(h);
    __half2 l = __floats2half2_rn(v.x - hf.x, v.y - hf.y);
    lo = *(uint32_t*)&l;
}
__device__ __forceinline__ void cp16(uint32_t dst, const void* src) {
    asm volatile("cp.async.cg.shared.global [%0], [%1], 16;" :: "r"(dst), "l"(src));
}
__device__ __forceinline__ void cp_commit() {
    asm volatile("cp.async.commit_group;" ::: "memory");
}

// ================= fp16 3-split GEMM (K1, K2): A,B K-major =================
// D[m,n] = sum_k A[m*lda+k]*B[n*ldb+k] (+bias[n]); near-fp32 accuracy.
#define HS 40                         // floats per smem row (32 data + 8 pad)
#define HTILE_B (128 * HS * 4)        // 20480
#define HSTAGE  (2 * HTILE_B)         // 40960
#define HNS 4
template<bool BIAS>
__global__ __launch_bounds__(256, 1)
void hgemm_split(const float* __restrict__ Aall, const float* __restrict__ Ball,
                 const float* __restrict__ bias, float* __restrict__ Call,
                 int K, int lda, int ldb, int ldc,
                 long strideA, long strideB, long strideC)
{
    extern __shared__ char smem_raw[];
    const uint32_t sbase = smem_u32(smem_raw);

    const int tid = threadIdx.x;
    const int lane = tid & 31;
    const int wid = tid >> 5;
    const int wm = wid & 1;
    const int wn = wid >> 1;
    const int g = lane >> 2;
    const int t = lane & 3;
    const int m0 = blockIdx.y * 128;
    const int n0 = blockIdx.x * 128;
    const float* A = Aall + (long)blockIdx.z * strideA;
    const float* B = Ball + (long)blockIdx.z * strideB;
    float* C = Call + (long)blockIdx.z * strideC;

    float acc[4][4][4];
    #pragma unroll
    for (int i = 0; i < 4; i++)
        #pragma unroll
        for (int j = 0; j < 4; j++)
            #pragma unroll
            for (int e = 0; e < 4; e++) acc[i][j][e] = 0.f;

    const int iters = K >> 5;

    auto issue = [&](int it) {
        const int k0 = it << 5;
        const uint32_t st = sbase + (it & (HNS - 1)) * HSTAGE;
        #pragma unroll
        for (int i = 0; i < 4; i++) {
            int ch = tid + 256 * i;
            int r = ch >> 3, c = ch & 7;
            cp16(st + r * (HS * 4) + c * 16, &A[(long)(m0 + r) * lda + k0 + c * 4]);
        }
        #pragma unroll
        for (int i = 0; i < 4; i++) {
            int ch = tid + 256 * i;
            int r = ch >> 3, c = ch & 7;
            cp16(st + HTILE_B + r * (HS * 4) + c * 16, &B[(long)(n0 + r) * ldb + k0 + c * 4]);
        }
    };

    auto compute = [&](int stage) {
        const float* As = (const float*)(smem_raw + (size_t)stage * HSTAGE);
        const float* Bs = (const float*)(smem_raw + (size_t)stage * HSTAGE + HTILE_B);
        const int ar = wm * 64;
        const int br = wn * 32;
        #pragma unroll
        for (int ks = 0; ks < 2; ks++) {           // two k16 chunks per 32-k tile
            const int k0f = ks * 16 + 2 * t;       // float offset of k-pair
            uint32_t ah[4][4], al[4][4], bh[4][2], bl[4][2];
            #pragma unroll
            for (int mt = 0; mt < 4; mt++) {
                const float* p0 = &As[(ar + mt * 16 + g) * HS];
                const float* p1 = &As[(ar + mt * 16 + g + 8) * HS];
                split_h2(*(const float2*)&p0[k0f],     ah[mt][0], al[mt][0]);
                split_h2(*(const float2*)&p1[k0f],     ah[mt][1], al[mt][1]);
                split_h2(*(const float2*)&p0[k0f + 8], ah[mt][2], al[mt][2]);
                split_h2(*(const float2*)&p1[k0f + 8], ah[mt][3], al[mt][3]);
            }
            #pragma unroll
            for (int nt = 0; nt < 4; nt++) {
                const float* p = &Bs[(br + nt * 8 + g) * HS];
                split_h2(*(const float2*)&p[k0f],     bh[nt][0], bl[nt][0]);
                split_h2(*(const float2*)&p[k0f + 8], bh[nt][1], bl[nt][1]);
            }
            #pragma unroll
            for (int mt = 0; mt < 4; mt++)
                #pragma unroll
                for (int nt = 0; nt < 4; nt++) {
                    mma_f16(acc[mt][nt], ah[mt], bh[nt]);
                    mma_f16(acc[mt][nt], al[mt], bh[nt]);
                    mma_f16(acc[mt][nt], ah[mt], bl[nt]);
                }
        }
    };

    #pragma unroll
    for (int s = 0; s < HNS - 1; s++) { issue(s); cp_commit(); }

    for (int it = 0; it < iters; ++it) {
        asm volatile("cp.async.wait_group %0;" :: "n"(HNS - 2) : "memory");
        __syncthreads();
        if (it + HNS - 1 < iters) issue(it + HNS - 1);
        cp_commit();
        compute(it & (HNS - 1));
    }

    #pragma unroll
    for (int mt = 0; mt < 4; mt++) {
        const int r0 = m0 + wm * 64 + mt * 16 + g;
        #pragma unroll
        for (int nt = 0; nt < 4; nt++) {
            const int col = n0 + wn * 32 + nt * 8 + 2 * t;
            float b0 = 0.f, b1 = 0.f;
            if (BIAS) { b0 = bias[col]; b1 = bias[col + 1]; }
            *(float2*)&C[(long)r0 * ldc + col] =
                make_float2(acc[mt][nt][0] + b0, acc[mt][nt][1] + b1);
            *(float2*)&C[(long)(r0 + 8) * ldc + col] =
                make_float2(acc[mt][nt][2] + b0, acc[mt][nt][3] + b1);
        }
    }
}

// ================= single-pass tf32 GEMM (K4, K5) =================
// XTRANS=0: X'[i,k]=X[i*ldx+k] -> smem [128][36]; XTRANS=1: X'[i,k]=X[k*ldx+i] -> smem [32][136]
template<int ATRANS, int BTRANS>
__global__ __launch_bounds__(256, 2)
void tgemm(const float* __restrict__ Aall, const float* __restrict__ Ball,
           float* __restrict__ Call,
           int K, int lda, int ldb, int ldc,
           long strideA, long strideB, long strideC)
{
    constexpr int NS = 3;
    constexpr int SA = ATRANS ? 136 : 36;
    constexpr int SB = BTRANS ? 136 : 36;
    constexpr int ABYTES = (ATRANS ? 32 * 136 : 128 * 36) * 4;
    constexpr int BBYTES = (BTRANS ? 32 * 136 : 128 * 36) * 4;
    constexpr int STAGE = ABYTES + BBYTES;

    extern __shared__ char smem_raw[];
    const uint32_t sbase = smem_u32(smem_raw);

    const int tid = threadIdx.x;
    const int lane = tid & 31;
    const int wid = tid >> 5;
    const int wm = wid & 1;
    const int wn = wid >> 1;
    const int g = lane >> 2;
    const int t = lane & 3;
    const int m0 = blockIdx.y * 128;
    const int n0 = blockIdx.x * 128;
    const float* A = Aall + (long)blockIdx.z * strideA;
    const float* B = Ball + (long)blockIdx.z * strideB;
    float* C = Call + (long)blockIdx.z * strideC;

    float acc[4][4][4];
    #pragma unroll
    for (int i = 0; i < 4; i++)
        #pragma unroll
        for (int j = 0; j < 4; j++)
            #pragma unroll
            for (int e = 0; e < 4; e++) acc[i][j][e] = 0.f;

    const int iters = K >> 5;

    auto issue = [&](int it) {
        const int k0 = it << 5;
        const uint32_t st = sbase + (it % NS) * STAGE;
        if (ATRANS == 0) {
            #pragma unroll
            for (int i = 0; i < 4; i++) {
                int ch = tid + 256 * i;
                int r = ch >> 3, c = ch & 7;
                cp16(st + r * (SA * 4) + c * 16, &A[(long)(m0 + r) * lda + k0 + c * 4]);
            }
        } else {
            #pragma unroll
            for (int i = 0; i < 4; i++) {
                int ch = tid + 256 * i;
                int r = ch >> 5, c = ch & 31;
                cp16(st + r * (SA * 4) + c * 16, &A[(long)(k0 + r) * lda + m0 + c * 4]);
            }
        }
        if (BTRANS == 0) {
            #pragma unroll
            for (int i = 0; i < 4; i++) {
                int ch = tid + 256 * i;
                int r = ch >> 3, c = ch & 7;
                cp16(st + ABYTES + r * (SB * 4) + c * 16, &B[(long)(n0 + r) * ldb + k0 + c * 4]);
            }
        } else {
            #pragma unroll
            for (int i = 0; i < 4; i++) {
                int ch = tid + 256 * i;
                int r = ch >> 5, c = ch & 31;
                cp16(st + ABYTES + r * (SB * 4) + c * 16, &B[(long)(k0 + r) * ldb + n0 + c * 4]);
            }
        }
    };

    auto compute = [&](int stage) {
        const float* As = (const float*)(smem_raw + (size_t)stage * STAGE);
        const float* Bs = (const float*)(smem_raw + (size_t)stage * STAGE + ABYTES);
        const int ar = wm * 64;
        const int br = wn * 32;
        #pragma unroll
        for (int ks = 0; ks < 4; ks++) {
            const int col = ks * 8 + t;
            uint32_t af[4][4], bf[4][2];
            #pragma unroll
            for (int mt = 0; mt < 4; mt++) {
                if (ATRANS == 0) {
                    const float* p0 = &As[(ar + mt * 16 + g) * 36];
                    const float* p1 = &As[(ar + mt * 16 + g + 8) * 36];
                    af[mt][0] = f2tf(p0[col]);
                    af[mt][1] = f2tf(p1[col]);
                    af[mt][2] = f2tf(p0[col + 4]);
                    af[mt][3] = f2tf(p1[col + 4]);
                } else {
                    const float* p0 = &As[col * 136 + ar + mt * 16 + g];
                    const float* p1 = &As[(col + 4) * 136 + ar + mt * 16 + g];
                    af[mt][0] = f2tf(p0[0]);
                    af[mt][1] = f2tf(p0[8]);
                    af[mt][2] = f2tf(p1[0]);
                    af[mt][3] = f2tf(p1[8]);
                }
            }
            #pragma unroll
            for (int nt = 0; nt < 4; nt++) {
                if (BTRANS == 0) {
                    const float* p = &Bs[(br + nt * 8 + g) * 36];
                    bf[nt][0] = f2tf(p[col]);
                    bf[nt][1] = f2tf(p[col + 4]);
                } else {
                    bf[nt][0] = f2tf(Bs[col * 136 + br + nt * 8 + g]);
                    bf[nt][1] = f2tf(Bs[(col + 4) * 136 + br + nt * 8 + g]);
                }
            }
            #pragma unroll
            for (int mt = 0; mt < 4; mt++)
                #pragma unroll
                for (int nt = 0; nt < 4; nt++)
                    mma_tf32(acc[mt][nt], af[mt], bf[nt]);
        }
    };

    #pragma unroll
    for (int s = 0; s < NS - 1; s++) { issue(s); cp_commit(); }

    for (int it = 0; it < iters; ++it) {
        asm volatile("cp.async.wait_group %0;" :: "n"(NS - 2) : "memory");
        __syncthreads();
        if (it + NS - 1 < iters) issue(it + NS - 1);
        cp_commit();
        compute(it % NS);
    }

    #pragma unroll
    for (int mt = 0; mt < 4; mt++) {
        const int r0 = m0 + wm * 64 + mt * 16 + g;
        #pragma unroll
        for (int nt = 0; nt < 4; nt++) {
            const int col = n0 + wn * 32 + nt * 8 + 2 * t;
            *(float2*)&C[(long)r0 * ldc + col] =
                make_float2(acc[mt][nt][0], acc[mt][nt][1]);
            *(float2*)&C[(long)(r0 + 8) * ldc + col] =
                make_float2(acc[mt][nt][2], acc[mt][nt][3]);
        }
    }
}

// ---------------- softmax over rows of 2048 (in place) ----------------
__global__ __launch_bounds__(256)
void softmax2048_kernel(float* __restrict__ attn)
{
    const long row = blockIdx.x;
    float* p = attn + row * (long)N2;
    const int tid = threadIdx.x;

    float4 v0 = *(const float4*)(p + tid * 8);
    float4 v1 = *(const float4*)(p + tid * 8 + 4);

    float mx = fmaxf(fmaxf(fmaxf(v0.x, v0.y), fmaxf(v0.z, v0.w)),
                     fmaxf(fmaxf(v1.x, v1.y), fmaxf(v1.z, v1.w)));
    __shared__ float red[8];
    #pragma unroll
    for (int o = 16; o > 0; o >>= 1) mx = fmaxf(mx, __shfl_xor_sync(0xffffffffu, mx, o));
    if ((tid & 31) == 0) red[tid >> 5] = mx;
    __syncthreads();
    mx = red[0];
    #pragma unroll
    for (int i = 1; i < 8; i++) mx = fmaxf(mx, red[i]);
    __syncthreads();

    float e0 = expf(v0.x - mx), e1 = expf(v0.y - mx), e2 = expf(v0.z - mx), e3 = expf(v0.w - mx);
    float e4 = expf(v1.x - mx), e5 = expf(v1.y - mx), e6 = expf(v1.z - mx), e7 = expf(v1.w - mx);
    float s = ((e0 + e1) + (e2 + e3)) + ((e4 + e5) + (e6 + e7));
    #pragma unroll
    for (int o = 16; o > 0; o >>= 1) s += __shfl_xor_sync(0xffffffffu, s, o);
    if ((tid & 31) == 0) red[tid >> 5] = s;
    __syncthreads();
    s = 0.f;
    #pragma unroll
    for (int i = 0; i < 8; i++) s += red[i];
    const float inv = 1.0f / s;

    v0.x = e0 * inv; v0.y = e1 * inv; v0.z = e2 * inv; v0.w = e3 * inv;
    v1.x = e4 * inv; v1.y = e5 * inv; v1.z = e6 * inv; v1.w = e7 * inv;
    *(float4*)(p + tid * 8) = v0;
    *(float4*)(p + tid * 8 + 4) = v1;
}

// ---------------- launcher ----------------
extern "C" void kernel_launch(void* const* d_in, const int* in_sizes, int n_in,
                              void* d_out, int out_size)
{
    const float* input1 = (const float*)d_in[0];   // [B, N1, D]
    const float* input2 = (const float*)d_in[1];   // [B, N2, D]
    const float* W_w    = (const float*)d_in[2];   // [D, D]
    const float* W_b    = (const float*)d_in[3];   // [D]

    float* out1 = (float*)d_out;                    // [B, N1, D]
    float* out2 = out1 + (long)BATCH * N1 * DIM;    // [B, N2, D]

    float* q = nullptr;
    float* attn = nullptr;
    cudaGetSymbolAddress((void**)&q, g_q);
    cudaGetSymbolAddress((void**)&attn, g_attn);

    const int SM_H  = HNS * HSTAGE;                  // 163840 (K1, K2)
    const int SM_01 = 3 * (128 * 36 + 32 * 136) * 4; // 107520 (K4)
    const int SM_11 = 3 * 2 * 32 * 136 * 4;          // 104448 (K5)

    cudaFuncSetAttribute(hgemm_split<true>,  cudaFuncAttributeMaxDynamicSharedMemorySize, SM_H);
    cudaFuncSetAttribute(hgemm_split<false>, cudaFuncAttributeMaxDynamicSharedMemorySize, SM_H);
    cudaFuncSetAttribute(tgemm<0, 1>, cudaFuncAttributeMaxDynamicSharedMemorySize, SM_01);
    cudaFuncSetAttribute(tgemm<1, 1>, cudaFuncAttributeMaxDynamicSharedMemorySize, SM_11);

    // K1: q = input1 @ W^T + b    [16384, 512], K=512  (fp16 3-split)
    hgemm_split<true><<<dim3(DIM / 128, (BATCH * N1) / 128, 1), 256, SM_H>>>(
        input1, W_w, W_b, q, DIM, DIM, DIM, DIM, 0L, 0L, 0L);

    // K2: scores = q @ input2^T   per batch [2048, 2048], K=512  (fp16 3-split)
    hgemm_split<false><<<dim3(N2 / 128, N1 / 128, BATCH), 256, SM_H>>>(
        q, input2, nullptr, attn, DIM, DIM, DIM, N2,
        (long)N1 * DIM, (long)N2 * DIM, (long)N1 * N2);

    // softmax rows (in place)
    softmax2048_kernel<<<BATCH * N1, 256>>>(attn);

    // K4: out1 = attn @ input2    per batch [2048, 512], K=2048  (single tf32)
    tgemm<0, 1><<<dim3(DIM / 128, N1 / 128, BATCH), 256, SM_01>>>(
        attn, input2, out1, N2, N2, DIM, DIM,
        (long)N1 * N2, (long)N2 * DIM, (long)N1 * DIM);

    // K5: out2 = attn^T @ input1  per batch [2048, 512], K=2048  (single tf32)
    tgemm<1, 1><<<dim3(DIM / 128, N2 / 128, BATCH), 256, SM_11>>>(
        attn, input1, out2, N1, N2, DIM, DIM,
        (long)N1 * N2, (long)N1 * DIM, (long)N2 * DIM);
}

// round 6
// speedup vs baseline: 2.6403x; 1.0453x over previous
#include <cuda_runtime.h>
#include <cuda_fp16.h>
#include <cstdint>
#include <math.h>

#define BATCH 8
#define N1 2048
#define N2 2048
#define DIM 512

// Scratch: q [B,N1,D] (32MB) and attn [B,N1,N2] (128MB)
__device__ float g_q[(size_t)BATCH * N1 * DIM];
__device__ float g_attn[(size_t)BATCH * N1 * N2];

// ---------------- helpers ----------------
__device__ __forceinline__ uint32_t smem_u32(const void* p) {
    uint32_t a;
    asm("{ .reg .u64 t; cvta.to.shared.u64 t, %1; cvt.u32.u64 %0, t; }" : "=r"(a) : "l"(p));
    return a;
}
__device__ __forceinline__ uint32_t f2tf(float x) {
    uint32_t r;
    asm("cvt.rna.tf32.f32 %0, %1;" : "=r"(r) : "f"(x));
    return r;
}
__device__ __forceinline__ void mma_tf32(float* c, const uint32_t* a, const uint32_t* b) {
    asm volatile(
        "mma.sync.aligned.m16n8k8.row.col.f32.tf32.tf32.f32 "
        "{%0,%1,%2,%3}, {%4,%5,%6,%7}, {%8,%9}, {%0,%1,%2,%3};"
        : "+f"(c[0]), "+f"(c[1]), "+f"(c[2]), "+f"(c[3])
        : "r"(a[0]), "r"(a[1]), "r"(a[2]), "r"(a[3]), "r"(b[0]), "r"(b[1]));
}
__device__ __forceinline__ void mma_f16(float* c, const uint32_t* a, const uint32_t* b) {
    asm volatile(
        "mma.sync.aligned.m16n8k16.row.col.f32.f16.f16.f32 "
        "{%0,%1,%2,%3}, {%4,%5,%6,%7}, {%8,%9}, {%0,%1,%2,%3};"
        : "+f"(c[0]), "+f"(c[1]), "+f"(c[2]), "+f"(c[3])
        : "r"(a[0]), "r"(a[1]), "r"(a[2]), "r"(a[3]), "r"(b[0]), "r"(b[1]));
}
// split float2 -> hi f16x2 + lo f16x2 (3-term Ozaki-style split)
__device__ __forceinline__ void split_h2(float2 v, uint32_t& hi, uint32_t& lo) {
    __half2 h = __float22half2_rn(v);
    hi = *(uint32_t*)&h;
    float2 hf = __half22float2(h);
    __half2 l = __floats2half2_rn(v.x - hf.x, v.y - hf.y);
    lo = *(uint32_t*)&l;
}
__device__ __forceinline__ void cp16(uint32_t dst, const void* src) {
    asm volatile("cp.async.cg.shared.global [%0], [%1], 16;" :: "r"(dst), "l"(src));
}
__device__ __forceinline__ void cp_commit() {
    asm volatile("cp.async.commit_group;" ::: "memory");
}
// all-FMA exp (no MUFU): e^x = e^f * 2^n, deg-6 Taylor, |f| <= ln2/2
__device__ __forceinline__ float fexp(float x) {
    x = fmaxf(x, -87.0f);
    float y = x * 1.44269504088896f;
    float n = rintf(y);
    float f = fmaf(n, -0.693147180559945f, x);   // x - n*ln2, |f| <= 0.3466
    float p = 1.3888889e-3f;
    p = fmaf(p, f, 8.3333333e-3f);
    p = fmaf(p, f, 4.1666667e-2f);
    p = fmaf(p, f, 1.6666667e-1f);
    p = fmaf(p, f, 0.5f);
    p = fmaf(p, f, 1.0f);
    p = fmaf(p, f, 1.0f);
    float s = __int_as_float(((int)n + 127) << 23);
    return p * s;
}

// ================= fp16 3-split GEMM (K1, K2): A,B K-major =================
// D[m,n] = sum_k A[m*lda+k]*B[n*ldb+k] (+bias[n]); near-fp32 accuracy.
#define HS 40                         // floats per smem row (32 data + 8 pad)
#define HTILE_B (128 * HS * 4)        // 20480
#define HSTAGE  (2 * HTILE_B)         // 40960
#define HNS 2
template<bool BIAS>
__global__ __launch_bounds__(256, 2)
void hgemm_split(const float* __restrict__ Aall, const float* __restrict__ Ball,
                 const float* __restrict__ bias, float* __restrict__ Call,
                 int K, int lda, int ldb, int ldc,
                 long strideA, long strideB, long strideC)
{
    extern __shared__ char smem_raw[];
    const uint32_t sbase = smem_u32(smem_raw);

    const int tid = threadIdx.x;
    const int lane = tid & 31;
    const int wid = tid >> 5;
    const int wm = wid & 1;
    const int wn = wid >> 1;
    const int g = lane >> 2;
    const int t = lane & 3;
    const int m0 = blockIdx.y * 128;
    const int n0 = blockIdx.x * 128;
    const float* A = Aall + (long)blockIdx.z * strideA;
    const float* B = Ball + (long)blockIdx.z * strideB;
    float* C = Call + (long)blockIdx.z * strideC;

    float acc[4][4][4];
    #pragma unroll
    for (int i = 0; i < 4; i++)
        #pragma unroll
        for (int j = 0; j < 4; j++)
            #pragma unroll
            for (int e = 0; e < 4; e++) acc[i][j][e] = 0.f;

    const int iters = K >> 5;

    auto issue = [&](int it) {
        const int k0 = it << 5;
        const uint32_t st = sbase + (it & (HNS - 1)) * HSTAGE;
        #pragma unroll
        for (int i = 0; i < 4; i++) {
            int ch = tid + 256 * i;
            int r = ch >> 3, c = ch & 7;
            cp16(st + r * (HS * 4) + c * 16, &A[(long)(m0 + r) * lda + k0 + c * 4]);
        }
        #pragma unroll
        for (int i = 0; i < 4; i++) {
            int ch = tid + 256 * i;
            int r = ch >> 3, c = ch & 7;
            cp16(st + HTILE_B + r * (HS * 4) + c * 16, &B[(long)(n0 + r) * ldb + k0 + c * 4]);
        }
    };

    auto compute = [&](int stage) {
        const float* As = (const float*)(smem_raw + (size_t)stage * HSTAGE);
        const float* Bs = (const float*)(smem_raw + (size_t)stage * HSTAGE + HTILE_B);
        const int ar = wm * 64;
        const int br = wn * 32;
        #pragma unroll
        for (int ks = 0; ks < 2; ks++) {           // two k16 chunks per 32-k tile
            const int k0f = ks * 16 + 2 * t;       // float offset of k-pair
            uint32_t ah[4][4], al[4][4], bh[4][2], bl[4][2];
            #pragma unroll
            for (int mt = 0; mt < 4; mt++) {
                const float* p0 = &As[(ar + mt * 16 + g) * HS];
                const float* p1 = &As[(ar + mt * 16 + g + 8) * HS];
                split_h2(*(const float2*)&p0[k0f],     ah[mt][0], al[mt][0]);
                split_h2(*(const float2*)&p1[k0f],     ah[mt][1], al[mt][1]);
                split_h2(*(const float2*)&p0[k0f + 8], ah[mt][2], al[mt][2]);
                split_h2(*(const float2*)&p1[k0f + 8], ah[mt][3], al[mt][3]);
            }
            #pragma unroll
            for (int nt = 0; nt < 4; nt++) {
                const float* p = &Bs[(br + nt * 8 + g) * HS];
                split_h2(*(const float2*)&p[k0f],     bh[nt][0], bl[nt][0]);
                split_h2(*(const float2*)&p[k0f + 8], bh[nt][1], bl[nt][1]);
            }
            #pragma unroll
            for (int mt = 0; mt < 4; mt++)
                #pragma unroll
                for (int nt = 0; nt < 4; nt++) {
                    mma_f16(acc[mt][nt], ah[mt], bh[nt]);
                    mma_f16(acc[mt][nt], al[mt], bh[nt]);
                    mma_f16(acc[mt][nt], ah[mt], bl[nt]);
                }
        }
    };

    #pragma unroll
    for (int s = 0; s < HNS - 1; s++) { issue(s); cp_commit(); }

    for (int it = 0; it < iters; ++it) {
        asm volatile("cp.async.wait_group %0;" :: "n"(HNS - 2) : "memory");
        __syncthreads();
        if (it + HNS - 1 < iters) issue(it + HNS - 1);
        cp_commit();
        compute(it & (HNS - 1));
    }

    #pragma unroll
    for (int mt = 0; mt < 4; mt++) {
        const int r0 = m0 + wm * 64 + mt * 16 + g;
        #pragma unroll
        for (int nt = 0; nt < 4; nt++) {
            const int col = n0 + wn * 32 + nt * 8 + 2 * t;
            float b0 = 0.f, b1 = 0.f;
            if (BIAS) { b0 = bias[col]; b1 = bias[col + 1]; }
            *(float2*)&C[(long)r0 * ldc + col] =
                make_float2(acc[mt][nt][0] + b0, acc[mt][nt][1] + b1);
            *(float2*)&C[(long)(r0 + 8) * ldc + col] =
                make_float2(acc[mt][nt][2] + b0, acc[mt][nt][3] + b1);
        }
    }
}

// ================= single-pass tf32 GEMM (K4, K5) =================
// XTRANS=0: X'[i,k]=X[i*ldx+k] -> smem [128][36]; XTRANS=1: X'[i,k]=X[k*ldx+i] -> smem [32][136]
template<int ATRANS, int BTRANS>
__global__ __launch_bounds__(256, 2)
void tgemm(const float* __restrict__ Aall, const float* __restrict__ Ball,
           float* __restrict__ Call,
           int K, int lda, int ldb, int ldc,
           long strideA, long strideB, long strideC)
{
    constexpr int NS = 3;
    constexpr int SA = ATRANS ? 136 : 36;
    constexpr int SB = BTRANS ? 136 : 36;
    constexpr int ABYTES = (ATRANS ? 32 * 136 : 128 * 36) * 4;
    constexpr int BBYTES = (BTRANS ? 32 * 136 : 128 * 36) * 4;
    constexpr int STAGE = ABYTES + BBYTES;

    extern __shared__ char smem_raw[];
    const uint32_t sbase = smem_u32(smem_raw);

    const int tid = threadIdx.x;
    const int lane = tid & 31;
    const int wid = tid >> 5;
    const int wm = wid & 1;
    const int wn = wid >> 1;
    const int g = lane >> 2;
    const int t = lane & 3;
    const int m0 = blockIdx.y * 128;
    const int n0 = blockIdx.x * 128;
    const float* A = Aall + (long)blockIdx.z * strideA;
    const float* B = Ball + (long)blockIdx.z * strideB;
    float* C = Call + (long)blockIdx.z * strideC;

    float acc[4][4][4];
    #pragma unroll
    for (int i = 0; i < 4; i++)
        #pragma unroll
        for (int j = 0; j < 4; j++)
            #pragma unroll
            for (int e = 0; e < 4; e++) acc[i][j][e] = 0.f;

    const int iters = K >> 5;

    auto issue = [&](int it) {
        const int k0 = it << 5;
        const uint32_t st = sbase + (it % NS) * STAGE;
        if (ATRANS == 0) {
            #pragma unroll
            for (int i = 0; i < 4; i++) {
                int ch = tid + 256 * i;
                int r = ch >> 3, c = ch & 7;
                cp16(st + r * (SA * 4) + c * 16, &A[(long)(m0 + r) * lda + k0 + c * 4]);
            }
        } else {
            #pragma unroll
            for (int i = 0; i < 4; i++) {
                int ch = tid + 256 * i;
                int r = ch >> 5, c = ch & 31;
                cp16(st + r * (SA * 4) + c * 16, &A[(long)(k0 + r) * lda + m0 + c * 4]);
            }
        }
        if (BTRANS == 0) {
            #pragma unroll
            for (int i = 0; i < 4; i++) {
                int ch = tid + 256 * i;
                int r = ch >> 3, c = ch & 7;
                cp16(st + ABYTES + r * (SB * 4) + c * 16, &B[(long)(n0 + r) * ldb + k0 + c * 4]);
            }
        } else {
            #pragma unroll
            for (int i = 0; i < 4; i++) {
                int ch = tid + 256 * i;
                int r = ch >> 5, c = ch & 31;
                cp16(st + ABYTES + r * (SB * 4) + c * 16, &B[(long)(k0 + r) * ldb + n0 + c * 4]);
            }
        }
    };

    auto compute = [&](int stage) {
        const float* As = (const float*)(smem_raw + (size_t)stage * STAGE);
        const float* Bs = (const float*)(smem_raw + (size_t)stage * STAGE + ABYTES);
        const int ar = wm * 64;
        const int br = wn * 32;
        #pragma unroll
        for (int ks = 0; ks < 4; ks++) {
            const int col = ks * 8 + t;
            uint32_t af[4][4], bf[4][2];
            #pragma unroll
            for (int mt = 0; mt < 4; mt++) {
                if (ATRANS == 0) {
                    const float* p0 = &As[(ar + mt * 16 + g) * 36];
                    const float* p1 = &As[(ar + mt * 16 + g + 8) * 36];
                    af[mt][0] = f2tf(p0[col]);
                    af[mt][1] = f2tf(p1[col]);
                    af[mt][2] = f2tf(p0[col + 4]);
                    af[mt][3] = f2tf(p1[col + 4]);
                } else {
                    const float* p0 = &As[col * 136 + ar + mt * 16 + g];
                    const float* p1 = &As[(col + 4) * 136 + ar + mt * 16 + g];
                    af[mt][0] = f2tf(p0[0]);
                    af[mt][1] = f2tf(p0[8]);
                    af[mt][2] = f2tf(p1[0]);
                    af[mt][3] = f2tf(p1[8]);
                }
            }
            #pragma unroll
            for (int nt = 0; nt < 4; nt++) {
                if (BTRANS == 0) {
                    const float* p = &Bs[(br + nt * 8 + g) * 36];
                    bf[nt][0] = f2tf(p[col]);
                    bf[nt][1] = f2tf(p[col + 4]);
                } else {
                    bf[nt][0] = f2tf(Bs[col * 136 + br + nt * 8 + g]);
                    bf[nt][1] = f2tf(Bs[(col + 4) * 136 + br + nt * 8 + g]);
                }
            }
            #pragma unroll
            for (int mt = 0; mt < 4; mt++)
                #pragma unroll
                for (int nt = 0; nt < 4; nt++)
                    mma_tf32(acc[mt][nt], af[mt], bf[nt]);
        }
    };

    #pragma unroll
    for (int s = 0; s < NS - 1; s++) { issue(s); cp_commit(); }

    for (int it = 0; it < iters; ++it) {
        asm volatile("cp.async.wait_group %0;" :: "n"(NS - 2) : "memory");
        __syncthreads();
        if (it + NS - 1 < iters) issue(it + NS - 1);
        cp_commit();
        compute(it % NS);
    }

    #pragma unroll
    for (int mt = 0; mt < 4; mt++) {
        const int r0 = m0 + wm * 64 + mt * 16 + g;
        #pragma unroll
        for (int nt = 0; nt < 4; nt++) {
            const int col = n0 + wn * 32 + nt * 8 + 2 * t;
            *(float2*)&C[(long)r0 * ldc + col] =
                make_float2(acc[mt][nt][0], acc[mt][nt][1]);
            *(float2*)&C[(long)(r0 + 8) * ldc + col] =
                make_float2(acc[mt][nt][2], acc[mt][nt][3]);
        }
    }
}

// ---------------- softmax over rows of 2048 (in place, FMA-only exp) ----------------
__global__ __launch_bounds__(256)
void softmax2048_kernel(float* __restrict__ attn)
{
    const long row = blockIdx.x;
    float* p = attn + row * (long)N2;
    const int tid = threadIdx.x;

    float4 v0 = *(const float4*)(p + tid * 8);
    float4 v1 = *(const float4*)(p + tid * 8 + 4);

    float mx = fmaxf(fmaxf(fmaxf(v0.x, v0.y), fmaxf(v0.z, v0.w)),
                     fmaxf(fmaxf(v1.x, v1.y), fmaxf(v1.z, v1.w)));
    __shared__ float red[8];
    #pragma unroll
    for (int o = 16; o > 0; o >>= 1) mx = fmaxf(mx, __shfl_xor_sync(0xffffffffu, mx, o));
    if ((tid & 31) == 0) red[tid >> 5] = mx;
    __syncthreads();
    mx = red[0];
    #pragma unroll
    for (int i = 1; i < 8; i++) mx = fmaxf(mx, red[i]);
    __syncthreads();

    float e0 = fexp(v0.x - mx), e1 = fexp(v0.y - mx), e2 = fexp(v0.z - mx), e3 = fexp(v0.w - mx);
    float e4 = fexp(v1.x - mx), e5 = fexp(v1.y - mx), e6 = fexp(v1.z - mx), e7 = fexp(v1.w - mx);
    float s = ((e0 + e1) + (e2 + e3)) + ((e4 + e5) + (e6 + e7));
    #pragma unroll
    for (int o = 16; o > 0; o >>= 1) s += __shfl_xor_sync(0xffffffffu, s, o);
    if ((tid & 31) == 0) red[tid >> 5] = s;
    __syncthreads();
    s = 0.f;
    #pragma unroll
    for (int i = 0; i < 8; i++) s += red[i];
    const float inv = 1.0f / s;

    v0.x = e0 * inv; v0.y = e1 * inv; v0.z = e2 * inv; v0.w = e3 * inv;
    v1.x = e4 * inv; v1.y = e5 * inv; v1.z = e6 * inv; v1.w = e7 * inv;
    *(float4*)(p + tid * 8) = v0;
    *(float4*)(p + tid * 8 + 4) = v1;
}

// ---------------- launcher ----------------
extern "C" void kernel_launch(void* const* d_in, const int* in_sizes, int n_in,
                              void* d_out, int out_size)
{
    const float* input1 = (const float*)d_in[0];   // [B, N1, D]
    const float* input2 = (const float*)d_in[1];   // [B, N2, D]
    const float* W_w    = (const float*)d_in[2];   // [D, D]
    const float* W_b    = (const float*)d_in[3];   // [D]

    float* out1 = (float*)d_out;                    // [B, N1, D]
    float* out2 = out1 + (long)BATCH * N1 * DIM;    // [B, N2, D]

    float* q = nullptr;
    float* attn = nullptr;
    cudaGetSymbolAddress((void**)&q, g_q);
    cudaGetSymbolAddress((void**)&attn, g_attn);

    const int SM_H  = HNS * HSTAGE;                  // 81920 (K1, K2) -> 2 CTAs/SM
    const int SM_01 = 3 * (128 * 36 + 32 * 136) * 4; // 107520 (K4)
    const int SM_11 = 3 * 2 * 32 * 136 * 4;          // 104448 (K5)

    cudaFuncSetAttribute(hgemm_split<true>,  cudaFuncAttributeMaxDynamicSharedMemorySize, SM_H);
    cudaFuncSetAttribute(hgemm_split<false>, cudaFuncAttributeMaxDynamicSharedMemorySize, SM_H);
    cudaFuncSetAttribute(tgemm<0, 1>, cudaFuncAttributeMaxDynamicSharedMemorySize, SM_01);
    cudaFuncSetAttribute(tgemm<1, 1>, cudaFuncAttributeMaxDynamicSharedMemorySize, SM_11);

    // K1: q = input1 @ W^T + b    [16384, 512], K=512  (fp16 3-split)
    hgemm_split<true><<<dim3(DIM / 128, (BATCH * N1) / 128, 1), 256, SM_H>>>(
        input1, W_w, W_b, q, DIM, DIM, DIM, DIM, 0L, 0L, 0L);

    // K2: scores = q @ input2^T   per batch [2048, 2048], K=512  (fp16 3-split)
    hgemm_split<false><<<dim3(N2 / 128, N1 / 128, BATCH), 256, SM_H>>>(
        q, input2, nullptr, attn, DIM, DIM, DIM, N2,
        (long)N1 * DIM, (long)N2 * DIM, (long)N1 * N2);

    // softmax rows (in place)
    softmax2048_kernel<<<BATCH * N1, 256>>>(attn);

    // K4: out1 = attn @ input2    per batch [2048, 512], K=2048  (single tf32)
    tgemm<0, 1><<<dim3(DIM / 128, N1 / 128, BATCH), 256, SM_01>>>(
        attn, input2, out1, N2, N2, DIM, DIM,
        (long)N1 * N2, (long)N2 * DIM, (long)N1 * DIM);

    // K5: out2 = attn^T @ input1  per batch [2048, 512], K=2048  (single tf32)
    tgemm<1, 1><<<dim3(DIM / 128, N2 / 128, BATCH), 256, SM_11>>>(
        attn, input1, out2, N1, N2, DIM, DIM,
        (long)N1 * N2, (long)N1 * DIM, (long)N2 * DIM);
}

// round 7
// speedup vs baseline: 3.3416x; 1.2656x over previous
#include <cuda_runtime.h>
#include <cuda_fp16.h>
#include <cstdint>
#include <math.h>

#define BATCH 8
#define N1 2048
#define N2 2048
#define DIM 512

// Scratch
__device__ float  g_q[(size_t)BATCH * N1 * DIM];                 // 32MB
__device__ float  g_attn[(size_t)BATCH * N1 * N2];               // 128MB logits
__device__ __half g_attn_h[(size_t)BATCH * N1 * N2];             // 64MB
__device__ __half g_attn_hT[(size_t)BATCH * N1 * N2];            // 64MB
__device__ __half g_in1T[(size_t)BATCH * DIM * N1];              // 16MB
__device__ __half g_in2T[(size_t)BATCH * DIM * N2];              // 16MB

// ---------------- helpers ----------------
__device__ __forceinline__ uint32_t smem_u32(const void* p) {
    uint32_t a;
    asm("{ .reg .u64 t; cvta.to.shared.u64 t, %1; cvt.u32.u64 %0, t; }" : "=r"(a) : "l"(p));
    return a;
}
__device__ __forceinline__ void mma_f16(float* c, const uint32_t* a, const uint32_t* b) {
    asm volatile(
        "mma.sync.aligned.m16n8k16.row.col.f32.f16.f16.f32 "
        "{%0,%1,%2,%3}, {%4,%5,%6,%7}, {%8,%9}, {%0,%1,%2,%3};"
        : "+f"(c[0]), "+f"(c[1]), "+f"(c[2]), "+f"(c[3])
        : "r"(a[0]), "r"(a[1]), "r"(a[2]), "r"(a[3]), "r"(b[0]), "r"(b[1]));
}
// split float2 -> hi f16x2 + lo f16x2
__device__ __forceinline__ void split_h2(float2 v, uint32_t& hi, uint32_t& lo) {
    __half2 h = __float22half2_rn(v);
    hi = *(uint32_t*)&h;
    float2 hf = __half22float2(h);
    __half2 l = __floats2half2_rn(v.x - hf.x, v.y - hf.y);
    lo = *(uint32_t*)&l;
}
__device__ __forceinline__ void cp16(uint32_t dst, const void* src) {
    asm volatile("cp.async.cg.shared.global [%0], [%1], 16;" :: "r"(dst), "l"(src));
}
__device__ __forceinline__ void cp_commit() {
    asm volatile("cp.async.commit_group;" ::: "memory");
}
// all-FMA exp (no MUFU)
__device__ __forceinline__ float fexp(float x) {
    x = fmaxf(x, -87.0f);
    float n = rintf(x * 1.44269504088896f);
    float f = fmaf(n, -0.693147180559945f, x);
    float p = 1.3888889e-3f;
    p = fmaf(p, f, 8.3333333e-3f);
    p = fmaf(p, f, 4.1666667e-2f);
    p = fmaf(p, f, 1.6666667e-1f);
    p = fmaf(p, f, 0.5f);
    p = fmaf(p, f, 1.0f);
    p = fmaf(p, f, 1.0f);
    return p * __int_as_float(((int)n + 127) << 23);
}

// ================= fp16 3-split GEMM (K1, K2): A,B K-major fp32 =================
#define HS 40
#define HTILE_B (128 * HS * 4)
#define HSTAGE  (2 * HTILE_B)
#define HNS 2
template<bool BIAS>
__global__ __launch_bounds__(256, 2)
void hgemm_split(const float* __restrict__ Aall, const float* __restrict__ Ball,
                 const float* __restrict__ bias, float* __restrict__ Call,
                 int K, int lda, int ldb, int ldc,
                 long strideA, long strideB, long strideC)
{
    extern __shared__ char smem_raw[];
    const uint32_t sbase = smem_u32(smem_raw);

    const int tid = threadIdx.x;
    const int lane = tid & 31;
    const int wid = tid >> 5;
    const int wm = wid & 1;
    const int wn = wid >> 1;
    const int g = lane >> 2;
    const int t = lane & 3;
    const int m0 = blockIdx.y * 128;
    const int n0 = blockIdx.x * 128;
    const float* A = Aall + (long)blockIdx.z * strideA;
    const float* B = Ball + (long)blockIdx.z * strideB;
    float* C = Call + (long)blockIdx.z * strideC;

    float acc[4][4][4];
    #pragma unroll
    for (int i = 0; i < 4; i++)
        #pragma unroll
        for (int j = 0; j < 4; j++)
            #pragma unroll
            for (int e = 0; e < 4; e++) acc[i][j][e] = 0.f;

    const int iters = K >> 5;

    auto issue = [&](int it) {
        const int k0 = it << 5;
        const uint32_t st = sbase + (it & (HNS - 1)) * HSTAGE;
        #pragma unroll
        for (int i = 0; i < 4; i++) {
            int ch = tid + 256 * i;
            int r = ch >> 3, c = ch & 7;
            cp16(st + r * (HS * 4) + c * 16, &A[(long)(m0 + r) * lda + k0 + c * 4]);
        }
        #pragma unroll
        for (int i = 0; i < 4; i++) {
            int ch = tid + 256 * i;
            int r = ch >> 3, c = ch & 7;
            cp16(st + HTILE_B + r * (HS * 4) + c * 16, &B[(long)(n0 + r) * ldb + k0 + c * 4]);
        }
    };

    auto compute = [&](int stage) {
        const float* As = (const float*)(smem_raw + (size_t)stage * HSTAGE);
        const float* Bs = (const float*)(smem_raw + (size_t)stage * HSTAGE + HTILE_B);
        const int ar = wm * 64;
        const int br = wn * 32;
        #pragma unroll
        for (int ks = 0; ks < 2; ks++) {
            const int k0f = ks * 16 + 2 * t;
            uint32_t ah[4][4], al[4][4], bh[4][2], bl[4][2];
            #pragma unroll
            for (int mt = 0; mt < 4; mt++) {
                const float* p0 = &As[(ar + mt * 16 + g) * HS];
                const float* p1 = &As[(ar + mt * 16 + g + 8) * HS];
                split_h2(*(const float2*)&p0[k0f],     ah[mt][0], al[mt][0]);
                split_h2(*(const float2*)&p1[k0f],     ah[mt][1], al[mt][1]);
                split_h2(*(const float2*)&p0[k0f + 8], ah[mt][2], al[mt][2]);
                split_h2(*(const float2*)&p1[k0f + 8], ah[mt][3], al[mt][3]);
            }
            #pragma unroll
            for (int nt = 0; nt < 4; nt++) {
                const float* p = &Bs[(br + nt * 8 + g) * HS];
                split_h2(*(const float2*)&p[k0f],     bh[nt][0], bl[nt][0]);
                split_h2(*(const float2*)&p[k0f + 8], bh[nt][1], bl[nt][1]);
            }
            #pragma unroll
            for (int mt = 0; mt < 4; mt++)
                #pragma unroll
                for (int nt = 0; nt < 4; nt++) {
                    mma_f16(acc[mt][nt], ah[mt], bh[nt]);
                    mma_f16(acc[mt][nt], al[mt], bh[nt]);
                    mma_f16(acc[mt][nt], ah[mt], bl[nt]);
                }
        }
    };

    #pragma unroll
    for (int s = 0; s < HNS - 1; s++) { issue(s); cp_commit(); }

    for (int it = 0; it < iters; ++it) {
        asm volatile("cp.async.wait_group %0;" :: "n"(HNS - 2) : "memory");
        __syncthreads();
        if (it + HNS - 1 < iters) issue(it + HNS - 1);
        cp_commit();
        compute(it & (HNS - 1));
    }

    #pragma unroll
    for (int mt = 0; mt < 4; mt++) {
        const int r0 = m0 + wm * 64 + mt * 16 + g;
        #pragma unroll
        for (int nt = 0; nt < 4; nt++) {
            const int col = n0 + wn * 32 + nt * 8 + 2 * t;
            float b0 = 0.f, b1 = 0.f;
            if (BIAS) { b0 = bias[col]; b1 = bias[col + 1]; }
            *(float2*)&C[(long)r0 * ldc + col] =
                make_float2(acc[mt][nt][0] + b0, acc[mt][nt][1] + b1);
            *(float2*)&C[(long)(r0 + 8) * ldc + col] =
                make_float2(acc[mt][nt][2] + b0, acc[mt][nt][3] + b1);
        }
    }
}

// ================= fp16 single-pass GEMM (K4, K5): A,B K-major fp16 =================
// D[m,n] = sum_k Ah[m*lda+k] * Bh[n*ldb+k]; fp32 accumulate, fp32 out.
#define GS 40                          // halfs per smem row (32 data + 8 pad)
#define GTILE_B (128 * GS * 2)         // 10240 bytes
#define GSTAGE  (2 * GTILE_B)          // 20480
#define GNS 4
__global__ __launch_bounds__(256, 2)
void tgemm_h(const __half* __restrict__ Aall, const __half* __restrict__ Ball,
             float* __restrict__ Call,
             int K, int lda, int ldb, int ldc,
             long strideA, long strideB, long strideC)
{
    extern __shared__ char smem_raw[];
    const uint32_t sbase = smem_u32(smem_raw);

    const int tid = threadIdx.x;
    const int lane = tid & 31;
    const int wid = tid >> 5;
    const int wm = wid & 1;
    const int wn = wid >> 1;
    const int g = lane >> 2;
    const int t = lane & 3;
    const int m0 = blockIdx.y * 128;
    const int n0 = blockIdx.x * 128;
    const __half* A = Aall + (long)blockIdx.z * strideA;
    const __half* B = Ball + (long)blockIdx.z * strideB;
    float* C = Call + (long)blockIdx.z * strideC;

    float acc[4][4][4];
    #pragma unroll
    for (int i = 0; i < 4; i++)
        #pragma unroll
        for (int j = 0; j < 4; j++)
            #pragma unroll
            for (int e = 0; e < 4; e++) acc[i][j][e] = 0.f;

    const int iters = K >> 5;

    auto issue = [&](int it) {
        const int k0 = it << 5;
        const uint32_t st = sbase + (it & (GNS - 1)) * GSTAGE;
        #pragma unroll
        for (int i = 0; i < 2; i++) {
            int ch = tid + 256 * i;
            int r = ch >> 2, c = ch & 3;
            cp16(st + r * (GS * 2) + c * 16, &A[(long)(m0 + r) * lda + k0 + c * 8]);
        }
        #pragma unroll
        for (int i = 0; i < 2; i++) {
            int ch = tid + 256 * i;
            int r = ch >> 2, c = ch & 3;
            cp16(st + GTILE_B + r * (GS * 2) + c * 16, &B[(long)(n0 + r) * ldb + k0 + c * 8]);
        }
    };

    auto compute = [&](int stage) {
        const __half* As = (const __half*)(smem_raw + (size_t)stage * GSTAGE);
        const __half* Bs = (const __half*)(smem_raw + (size_t)stage * GSTAGE + GTILE_B);
        const int ar = wm * 64;
        const int br = wn * 32;
        #pragma unroll
        for (int ks = 0; ks < 2; ks++) {
            const int k0h = ks * 16 + 2 * t;
            uint32_t a[4][4], b[4][2];
            #pragma unroll
            for (int mt = 0; mt < 4; mt++) {
                const __half* p0 = &As[(ar + mt * 16 + g) * GS];
                const __half* p1 = &As[(ar + mt * 16 + g + 8) * GS];
                a[mt][0] = *(const uint32_t*)&p0[k0h];
                a[mt][1] = *(const uint32_t*)&p1[k0h];
                a[mt][2] = *(const uint32_t*)&p0[k0h + 8];
                a[mt][3] = *(const uint32_t*)&p1[k0h + 8];
            }
            #pragma unroll
            for (int nt = 0; nt < 4; nt++) {
                const __half* p = &Bs[(br + nt * 8 + g) * GS];
                b[nt][0] = *(const uint32_t*)&p[k0h];
                b[nt][1] = *(const uint32_t*)&p[k0h + 8];
            }
            #pragma unroll
            for (int mt = 0; mt < 4; mt++)
                #pragma unroll
                for (int nt = 0; nt < 4; nt++)
                    mma_f16(acc[mt][nt], a[mt], b[nt]);
        }
    };

    #pragma unroll
    for (int s = 0; s < GNS - 1; s++) { issue(s); cp_commit(); }

    for (int it = 0; it < iters; ++it) {
        asm volatile("cp.async.wait_group %0;" :: "n"(GNS - 2) : "memory");
        __syncthreads();
        if (it + GNS - 1 < iters) issue(it + GNS - 1);
        cp_commit();
        compute(it & (GNS - 1));
    }

    #pragma unroll
    for (int mt = 0; mt < 4; mt++) {
        const int r0 = m0 + wm * 64 + mt * 16 + g;
        #pragma unroll
        for (int nt = 0; nt < 4; nt++) {
            const int col = n0 + wn * 32 + nt * 8 + 2 * t;
            *(float2*)&C[(long)r0 * ldc + col] = make_float2(acc[mt][nt][0], acc[mt][nt][1]);
            *(float2*)&C[(long)(r0 + 8) * ldc + col] = make_float2(acc[mt][nt][2], acc[mt][nt][3]);
        }
    }
}

// ---------------- softmax rows of 2048: fp32 logits in -> fp16 attn out ----------------
__global__ __launch_bounds__(256)
void softmax2048_kernel(const float* __restrict__ logits, __half* __restrict__ attn_h)
{
    const long row = blockIdx.x;
    const float* p = logits + row * (long)N2;
    const int tid = threadIdx.x;

    float4 v0 = *(const float4*)(p + tid * 8);
    float4 v1 = *(const float4*)(p + tid * 8 + 4);

    float mx = fmaxf(fmaxf(fmaxf(v0.x, v0.y), fmaxf(v0.z, v0.w)),
                     fmaxf(fmaxf(v1.x, v1.y), fmaxf(v1.z, v1.w)));
    __shared__ float red[8];
    #pragma unroll
    for (int o = 16; o > 0; o >>= 1) mx = fmaxf(mx, __shfl_xor_sync(0xffffffffu, mx, o));
    if ((tid & 31) == 0) red[tid >> 5] = mx;
    __syncthreads();
    mx = red[0];
    #pragma unroll
    for (int i = 1; i < 8; i++) mx = fmaxf(mx, red[i]);
    __syncthreads();

    float e0 = fexp(v0.x - mx), e1 = fexp(v0.y - mx), e2 = fexp(v0.z - mx), e3 = fexp(v0.w - mx);
    float e4 = fexp(v1.x - mx), e5 = fexp(v1.y - mx), e6 = fexp(v1.z - mx), e7 = fexp(v1.w - mx);
    float s = ((e0 + e1) + (e2 + e3)) + ((e4 + e5) + (e6 + e7));
    #pragma unroll
    for (int o = 16; o > 0; o >>= 1) s += __shfl_xor_sync(0xffffffffu, s, o);
    if ((tid & 31) == 0) red[tid >> 5] = s;
    __syncthreads();
    s = 0.f;
    #pragma unroll
    for (int i = 0; i < 8; i++) s += red[i];
    const float inv = 1.0f / s;

    __half2 h[4];
    h[0] = __floats2half2_rn(e0 * inv, e1 * inv);
    h[1] = __floats2half2_rn(e2 * inv, e3 * inv);
    h[2] = __floats2half2_rn(e4 * inv, e5 * inv);
    h[3] = __floats2half2_rn(e6 * inv, e7 * inv);
    *(uint4*)(attn_h + row * (long)N2 + tid * 8) = *(uint4*)h;
}

// ---------------- fp16 transpose: in [R x Cols] -> out [Cols x R], per batch z ----------------
// 64x64 tiles, 256 threads.
__global__ __launch_bounds__(256)
void transpose_h(const __half* __restrict__ in, __half* __restrict__ out, int R, int Cc)
{
    __shared__ __half S[64][65];
    const long zin = (long)blockIdx.z * R * Cc;
    const int x0 = blockIdx.x * 64;   // col tile
    const int y0 = blockIdx.y * 64;   // row tile
    const int tid = threadIdx.x;

    #pragma unroll
    for (int i = 0; i < 8; i++) {
        int idx = tid + 256 * i;
        int r = idx >> 5, c2 = idx & 31;
        __half2 v = *(const __half2*)&in[zin + (long)(y0 + r) * Cc + x0 + 2 * c2];
        S[r][2 * c2] = __low2half(v);
        S[r][2 * c2 + 1] = __high2half(v);
    }
    __syncthreads();
    #pragma unroll
    for (int i = 0; i < 8; i++) {
        int idx = tid + 256 * i;
        int cc = idx >> 5, r2 = idx & 31;
        __half2 v = __halves2half2(S[2 * r2][cc], S[2 * r2 + 1][cc]);
        *(__half2*)&out[zin + (long)(x0 + cc) * R + y0 + 2 * r2] = v;
    }
}

// ---------------- fp32 -> fp16 transpose: in [R x Cols] fp32 -> out [Cols x R] half ----------------
__global__ __launch_bounds__(256)
void transpose_f2h(const float* __restrict__ in, __half* __restrict__ out, int R, int Cc)
{
    __shared__ __half S[64][65];
    const long zo = (long)blockIdx.z * R * Cc;
    const int x0 = blockIdx.x * 64;
    const int y0 = blockIdx.y * 64;
    const int tid = threadIdx.x;

    #pragma unroll
    for (int i = 0; i < 8; i++) {
        int idx = tid + 256 * i;
        int r = idx >> 5, c2 = idx & 31;
        float2 v = *(const float2*)&in[zo + (long)(y0 + r) * Cc + x0 + 2 * c2];
        S[r][2 * c2] = __float2half_rn(v.x);
        S[r][2 * c2 + 1] = __float2half_rn(v.y);
    }
    __syncthreads();
    #pragma unroll
    for (int i = 0; i < 8; i++) {
        int idx = tid + 256 * i;
        int cc = idx >> 5, r2 = idx & 31;
        __half2 v = __halves2half2(S[2 * r2][cc], S[2 * r2 + 1][cc]);
        *(__half2*)&out[zo + (long)(x0 + cc) * R + y0 + 2 * r2] = v;
    }
}

// ---------------- launcher ----------------
extern "C" void kernel_launch(void* const* d_in, const int* in_sizes, int n_in,
                              void* d_out, int out_size)
{
    const float* input1 = (const float*)d_in[0];   // [B, N1, D]
    const float* input2 = (const float*)d_in[1];   // [B, N2, D]
    const float* W_w    = (const float*)d_in[2];   // [D, D]
    const float* W_b    = (const float*)d_in[3];   // [D]

    float* out1 = (float*)d_out;
    float* out2 = out1 + (long)BATCH * N1 * DIM;

    float *q, *attn;
    __half *attn_h, *attn_hT, *in1T, *in2T;
    cudaGetSymbolAddress((void**)&q, g_q);
    cudaGetSymbolAddress((void**)&attn, g_attn);
    cudaGetSymbolAddress((void**)&attn_h, g_attn_h);
    cudaGetSymbolAddress((void**)&attn_hT, g_attn_hT);
    cudaGetSymbolAddress((void**)&in1T, g_in1T);
    cudaGetSymbolAddress((void**)&in2T, g_in2T);

    const int SM_H = HNS * HSTAGE;     // 81920
    const int SM_G = GNS * GSTAGE;     // 81920

    cudaFuncSetAttribute(hgemm_split<true>,  cudaFuncAttributeMaxDynamicSharedMemorySize, SM_H);
    cudaFuncSetAttribute(hgemm_split<false>, cudaFuncAttributeMaxDynamicSharedMemorySize, SM_H);
    cudaFuncSetAttribute(tgemm_h, cudaFuncAttributeMaxDynamicSharedMemorySize, SM_G);

    // Prep: in1T[b][d][n] = input1[b][n][d], in2T likewise (fp16)
    transpose_f2h<<<dim3(DIM / 64, N1 / 64, BATCH), 256>>>(input1, in1T, N1, DIM);
    transpose_f2h<<<dim3(DIM / 64, N2 / 64, BATCH), 256>>>(input2, in2T, N2, DIM);

    // K1: q = input1 @ W^T + b   (fp16 3-split, near-fp32)
    hgemm_split<true><<<dim3(DIM / 128, (BATCH * N1) / 128, 1), 256, SM_H>>>(
        input1, W_w, W_b, q, DIM, DIM, DIM, DIM, 0L, 0L, 0L);

    // K2: logits = q @ input2^T  per batch (fp16 3-split)
    hgemm_split<false><<<dim3(N2 / 128, N1 / 128, BATCH), 256, SM_H>>>(
        q, input2, nullptr, attn, DIM, DIM, DIM, N2,
        (long)N1 * DIM, (long)N2 * DIM, (long)N1 * N2);

    // softmax: fp32 logits -> fp16 attn
    softmax2048_kernel<<<BATCH * N1, 256>>>(attn, attn_h);

    // attn_hT[b][m2][m1] = attn_h[b][m1][m2]
    transpose_h<<<dim3(N2 / 64, N1 / 64, BATCH), 256>>>(attn_h, attn_hT, N1, N2);

    // K4: out1 = attn @ input2   (fp16): A=attn_h [2048x2048], B=in2T [512x2048]
    tgemm_h<<<dim3(DIM / 128, N1 / 128, BATCH), 256, SM_G>>>(
        attn_h, in2T, out1, N2, N2, N2, DIM,
        (long)N1 * N2, (long)DIM * N2, (long)N1 * DIM);

    // K5: out2 = attn^T @ input1 (fp16): A=attn_hT, B=in1T
    tgemm_h<<<dim3(DIM / 128, N2 / 128, BATCH), 256, SM_G>>>(
        attn_hT, in1T, out2, N1, N1, N1, DIM,
        (long)N1 * N2, (long)DIM * N1, (long)N2 * DIM);
}